// round 14
// baseline (speedup 1.0000x reference)
#include <cuda_runtime.h>
#include <math.h>

#define NN      32768      // nodes
#define GG      128        // graphs
#define NPG     256        // nodes per graph
#define HID     128
#define NH      8
#define DH      16
#define EE      1048576    // edges
#define NLAYERS 3

typedef unsigned long long ull;
typedef unsigned int uint;
typedef unsigned short ushort;

// ---------------- packed f32x2 helpers ----------------
__device__ __forceinline__ ull pk2(float lo, float hi) {
    ull r; asm("mov.b64 %0,{%1,%2};" : "=l"(r) : "f"(lo), "f"(hi)); return r;
}
__device__ __forceinline__ void up2(ull v, float& lo, float& hi) {
    asm("mov.b64 {%0,%1},%2;" : "=f"(lo), "=f"(hi) : "l"(v));
}
__device__ __forceinline__ ull add2(ull a, ull b) {
    ull d; asm("add.rn.f32x2 %0,%1,%2;" : "=l"(d) : "l"(a), "l"(b)); return d;
}
__device__ __forceinline__ uint bf2(float lo, float hi) {
    uint r; asm("cvt.rn.bf16x2.f32 %0,%1,%2;" : "=r"(r) : "f"(hi), "f"(lo)); return r;
}
// bf16x2 word -> packed f32x2 (ull): lo half -> low float, hi half -> high float
__device__ __forceinline__ ull bfp2(uint u) {
    return ((ull)(u & 0xffff0000u) << 32) | ((ull)(u << 16));
}
__device__ __forceinline__ uint tf32(float x) {
    uint r; asm("cvt.rna.tf32.f32 %0,%1;" : "=r"(r) : "f"(x)); return r;
}
__device__ __forceinline__ float tf32f(float x) { return __uint_as_float(tf32(x)); }
__device__ __forceinline__ float trunc13(float x) {
    return __uint_as_float(__float_as_uint(x) & 0xffffe000u);
}
__device__ __forceinline__ void mma1688(float* c, uint a0, uint a1, uint a2, uint a3,
                                        uint b0, uint b1) {
    asm volatile("mma.sync.aligned.m16n8k8.row.col.f32.tf32.tf32.f32 "
        "{%0,%1,%2,%3},{%4,%5,%6,%7},{%8,%9},{%0,%1,%2,%3};"
        : "+f"(c[0]), "+f"(c[1]), "+f"(c[2]), "+f"(c[3])
        : "r"(a0), "r"(a1), "r"(a2), "r"(a3), "r"(b0), "r"(b1));
}
__device__ __forceinline__ void mmaf(float* c, float a0, float a1, float a2, float a3,
                                     float b0, float b1) {
    mma1688(c, __float_as_uint(a0), __float_as_uint(a1), __float_as_uint(a2),
            __float_as_uint(a3), __float_as_uint(b0), __float_as_uint(b1));
}
__device__ __forceinline__ void cpa16(uint dst, const void* src) {
    asm volatile("cp.async.ca.shared.global [%0], [%1], 16;" :: "r"(dst), "l"(src));
}
#define CP_COMMIT() asm volatile("cp.async.commit_group;" ::: "memory")
#define CP_WAIT(N)  asm volatile("cp.async.wait_group %0;" :: "n"(N) : "memory")

// ---------------- scratch (device globals; zero-initialized at module load) ----------------
__device__ float  g_h   [NN * HID];
__device__ float  g_h2  [NN * HID];
__device__ float  g_tmp [NN * HID];
__device__ float  g_q   [NN * HID];
__device__ float  g_k   [NN * HID];
__device__ float  g_v   [NN * HID];
__device__ ushort g_hwbf[NN * HID];
__device__ float  g_wct [NLAYERS * HID * HID];
__device__ int    g_deg[NN];        // zero at invocation start (cleanup re-zeros)
__device__ int    g_rp [NN + 1];
__device__ int    g_cur[NN];
__device__ int    g_col[EE];
__device__ float  g_dis[NN];
__device__ int    g_done[1];

// ---------------- kernel 1: hist + scan (last-block) + weight transpose ----------------
__global__ __launch_bounds__(256) void k_histscan_wt(const int* __restrict__ dst,
                        int* __restrict__ deg, int* __restrict__ rp,
                        int* __restrict__ cur, float* __restrict__ dis,
                        int* __restrict__ done,
                        const float* __restrict__ Wc, float* __restrict__ WT) {
    if (blockIdx.x >= 1024) {
        int w = (blockIdx.x - 1024) * 8 + (threadIdx.x >> 5);   // 0..383
        int l = w >> 7, f = w & 127;
        int lane = threadIdx.x & 31;
        const float* Wl = Wc + l * 16384;
        float4 v;
        v.x = __ldg(&Wl[(lane * 4 + 0) * 128 + f]);
        v.y = __ldg(&Wl[(lane * 4 + 1) * 128 + f]);
        v.z = __ldg(&Wl[(lane * 4 + 2) * 128 + f]);
        v.w = __ldg(&Wl[(lane * 4 + 3) * 128 + f]);
        *(float4*)&WT[(size_t)l * 16384 + f * 128 + lane * 4] = v;
        return;
    }
    int e = (blockIdx.x * 256 + threadIdx.x) * 4;
    int4 d = *(const int4*)&dst[e];
    atomicAdd(&deg[d.x], 1);
    atomicAdd(&deg[d.y], 1);
    atomicAdd(&deg[d.z], 1);
    atomicAdd(&deg[d.w], 1);
    __threadfence();
    __shared__ int amLast;
    if (threadIdx.x == 0)
        amLast = (atomicAdd(done, 1) == 1023);
    __syncthreads();
    if (!amLast) return;

    __shared__ int part[256];
    const int tid = threadIdx.x;
    const int base = tid * 128;
    int s = 0;
    for (int i = 0; i < 128; i++) s += deg[base + i];
    part[tid] = s;
    __syncthreads();
    for (int off = 1; off < 256; off <<= 1) {
        int t = (tid >= off) ? part[tid - off] : 0;
        __syncthreads();
        part[tid] += t;
        __syncthreads();
    }
    int run = part[tid] - s;
    for (int i = 0; i < 128; i++) {
        int d0 = deg[base + i];
        rp[base + i]  = run;
        cur[base + i] = run;
        dis[base + i] = rsqrtf((float)d0 + 1.0f);
        run += d0;
    }
    if (tid == 255) rp[NN] = run;
    if (tid == 0) *done = 0;
}

// ---------------- kernel 2: CSR fill + input projection ----------------
__global__ __launch_bounds__(256) void k_fill_proj(const int* __restrict__ src,
                       const int* __restrict__ dst,
                       int* __restrict__ cur, int* __restrict__ col,
                       const float* __restrict__ x, const float* __restrict__ W,
                       const float* __restrict__ b, const float* __restrict__ g,
                       const float* __restrict__ be, float* __restrict__ out) {
    if (blockIdx.x < 1024) {
        int e = (blockIdx.x * 256 + threadIdx.x) * 4;
        int4 s = *(const int4*)&src[e];
        int4 d = *(const int4*)&dst[e];
        int p0 = atomicAdd(&cur[d.x], 1);
        int p1 = atomicAdd(&cur[d.y], 1);
        int p2 = atomicAdd(&cur[d.z], 1);
        int p3 = atomicAdd(&cur[d.w], 1);
        col[p0] = s.x; col[p1] = s.y; col[p2] = s.z; col[p3] = s.w;
        return;
    }
    const int lane = threadIdx.x & 31;
    const int n0 = ((blockIdx.x - 1024) * 8 + (threadIdx.x >> 5)) * 8;
    float4 w[15];
    #pragma unroll
    for (int k = 0; k < 15; k++) w[k] = *(const float4*)&W[k * 128 + lane * 4];
    const float4 bb = *(const float4*)&b[lane * 4];
    const float4 gv = *(const float4*)&g[lane * 4];
    const float4 bv = *(const float4*)&be[lane * 4];
    float4 xv = make_float4(0.f, 0.f, 0.f, 0.f);
    if (lane < 30) xv = *(const float4*)&x[n0 * 15 + lane * 4];

    #pragma unroll
    for (int i = 0; i < 8; i++) {
        float4 acc = bb;
        #pragma unroll
        for (int k = 0; k < 15; k++) {
            const int e = i * 15 + k;
            const int srcLane = e >> 2, comp = e & 3;
            float xe = (comp == 0) ? xv.x : (comp == 1) ? xv.y : (comp == 2) ? xv.z : xv.w;
            float xk = __shfl_sync(0xffffffffu, xe, srcLane);
            acc.x = fmaf(xk, w[k].x, acc.x); acc.y = fmaf(xk, w[k].y, acc.y);
            acc.z = fmaf(xk, w[k].z, acc.z); acc.w = fmaf(xk, w[k].w, acc.w);
        }
        float s  = acc.x + acc.y + acc.z + acc.w;
        float s2 = acc.x*acc.x + acc.y*acc.y + acc.z*acc.z + acc.w*acc.w;
        #pragma unroll
        for (int o = 16; o > 0; o >>= 1) {
            s  += __shfl_xor_sync(0xffffffffu, s,  o);
            s2 += __shfl_xor_sync(0xffffffffu, s2, o);
        }
        float m   = s * (1.0f / 128.0f);
        float var = s2 * (1.0f / 128.0f) - m * m;
        float r   = rsqrtf(var + 1e-5f);
        float4 y;
        y.x = fmaxf((acc.x - m) * r * gv.x + bv.x, 0.0f);
        y.y = fmaxf((acc.y - m) * r * gv.y + bv.y, 0.0f);
        y.z = fmaxf((acc.z - m) * r * gv.z + bv.z, 0.0f);
        y.w = fmaxf((acc.w - m) * r * gv.w + bv.w, 0.0f);
        *(float4*)(out + (size_t)(n0 + i) * 128 + lane * 4) = y;
    }
}

// ---------------- tf32 tensor-core GEMM (3-stage cp.async pipeline) ----------------
// BM=128, BN=128, BK=32, 4 k-tiles, 3 smem stage buffers (s mod 3).
// 256 threads = 8 warps (2m x 4n), warp tile 64x32.
// BF16OUT=1: output row r scaled by dis[r], stored bf16 (GCN pre-scaled rows).
#define STG_W 4096

__device__ __forceinline__ void stage_issue(uint smA, uint smB,
                                            const float* __restrict__ A,
                                            const float* __restrict__ B,
                                            int row0, int kt, int t) {
    #pragma unroll
    for (int i = 0; i < 4; i++) {
        int idx = i * 256 + t;
        int r = idx >> 3, c4 = (idx & 7) * 4;
        int cs = c4 ^ ((r & 7) << 2);
        cpa16(smA + (uint)(r * 32 + cs) * 4u, &A[(size_t)(row0 + r) * 128 + kt * 32 + c4]);
    }
    #pragma unroll
    for (int i = 0; i < 4; i++) {
        int idx = i * 256 + t;
        int r = idx >> 3, c4 = (idx & 7) * 4;
        int cs = c4 ^ ((r & 7) << 2);
        cpa16(smB + (uint)(r * 32 + cs) * 4u, &B[(size_t)r * 128 + kt * 32 + c4]);
    }
}

template <int BIAS, int BF16OUT>
__device__ __forceinline__ void tgemm_dev(uint* sm, const float* __restrict__ A,
                                          const float* __restrict__ B,
                                          const float* __restrict__ bias,
                                          const float* __restrict__ dis,
                                          void* __restrict__ Cv) {
    const int t = threadIdx.x;
    const int lane = t & 31, warp = t >> 5;
    const int row0 = blockIdx.x * 128;
    const int m0 = (warp >> 2) * 64;
    const int n0 = (warp & 3) * 32;
    const int gid = lane >> 2, tg = lane & 3;
    const uint smbase = (uint)__cvta_generic_to_shared(sm);

    // prologue: stages 0,1,2 into buffers 0,1,2
    #pragma unroll
    for (int s = 0; s < 3; s++) {
        uint ab = smbase + (uint)s * 2u * STG_W * 4u;
        stage_issue(ab, ab + STG_W * 4u, A, B, row0, s, t);
        CP_COMMIT();
    }

    float acc[4][4][4];
    #pragma unroll
    for (int mi = 0; mi < 4; mi++)
        #pragma unroll
        for (int ni = 0; ni < 4; ni++)
            #pragma unroll
            for (int q = 0; q < 4; q++) acc[mi][ni][q] = 0.0f;

    #pragma unroll
    for (int kt = 0; kt < 4; kt++) {
        if (kt < 2)      { CP_WAIT(2); }
        else if (kt == 2){ CP_WAIT(1); }
        else             { CP_WAIT(0); }
        __syncthreads();
        const uint* As = sm + (kt % 3) * 2 * STG_W;
        const uint* Bs = As + STG_W;
        #pragma unroll
        for (int ks = 0; ks < 4; ks++) {
            const int c0 = (ks * 8 + tg) ^ (gid << 2);
            const int c1 = c0 ^ 4;
            uint af[4][4];
            #pragma unroll
            for (int mi = 0; mi < 4; mi++) {
                const uint* a0 = &As[(m0 + mi * 16 + gid) * 32];
                const uint* a1 = &As[(m0 + mi * 16 + gid + 8) * 32];
                af[mi][0] = a0[c0]; af[mi][1] = a1[c0];
                af[mi][2] = a0[c1]; af[mi][3] = a1[c1];
            }
            uint bf[4][2];
            #pragma unroll
            for (int ni = 0; ni < 4; ni++) {
                const uint* b0 = &Bs[(n0 + ni * 8 + gid) * 32];
                bf[ni][0] = b0[c0]; bf[ni][1] = b0[c1];
            }
            #pragma unroll
            for (int mi = 0; mi < 4; mi++)
                #pragma unroll
                for (int ni = 0; ni < 4; ni++)
                    mma1688(acc[mi][ni], af[mi][0], af[mi][1], af[mi][2], af[mi][3],
                            bf[ni][0], bf[ni][1]);
        }
        __syncthreads();
        if (kt < 1) {                       // stage 3 -> buffer 0 (just freed)
            int s = kt + 3;
            uint ab = smbase + (uint)(s % 3) * 2u * STG_W * 4u;
            stage_issue(ab, ab + STG_W * 4u, A, B, row0, s, t);
            CP_COMMIT();
        }
    }

    float2 bb[4];
    #pragma unroll
    for (int ni = 0; ni < 4; ni++) {
        if (BIAS) bb[ni] = *(const float2*)&bias[n0 + ni * 8 + tg * 2];
        else      bb[ni] = make_float2(0.f, 0.f);
    }
    #pragma unroll
    for (int mi = 0; mi < 4; mi++) {
        int r = row0 + m0 + mi * 16 + gid;
        float d0 = 1.0f, d1 = 1.0f;
        if (BF16OUT) { d0 = __ldg(&dis[r]); d1 = __ldg(&dis[r + 8]); }
        #pragma unroll
        for (int ni = 0; ni < 4; ni++) {
            int c = n0 + ni * 8 + tg * 2;
            float v0 = acc[mi][ni][0] + bb[ni].x;
            float v1 = acc[mi][ni][1] + bb[ni].y;
            float v2 = acc[mi][ni][2] + bb[ni].x;
            float v3 = acc[mi][ni][3] + bb[ni].y;
            if (BF16OUT) {
                ushort* Cb = (ushort*)Cv;
                *(uint*)(Cb + (size_t)r * 128 + c)       = bf2(v0 * d0, v1 * d0);
                *(uint*)(Cb + (size_t)(r + 8) * 128 + c) = bf2(v2 * d1, v3 * d1);
            } else {
                float* C = (float*)Cv;
                *(float2*)&C[(size_t)r * 128 + c]       = make_float2(v0, v1);
                *(float2*)&C[(size_t)(r + 8) * 128 + c] = make_float2(v2, v3);
            }
        }
    }
}

template <int BIAS, int BF16OUT>
__global__ __launch_bounds__(256, 2) void k_tgemm(const float* __restrict__ A,
                                                  const float* __restrict__ B,
                                                  const float* __restrict__ bias,
                                                  const float* __restrict__ dis,
                                                  void* __restrict__ C) {
    extern __shared__ uint smx[];
    tgemm_dev<BIAS, BF16OUT>(smx, A, B, bias, dis, C);
}

__global__ __launch_bounds__(256, 2) void k_tgemm_qkv(const float* __restrict__ A,
    const float* __restrict__ Wq, const float* __restrict__ bq, float* __restrict__ q,
    const float* __restrict__ Wk, const float* __restrict__ bk, float* __restrict__ k,
    const float* __restrict__ Wv, const float* __restrict__ bv, float* __restrict__ v) {
    extern __shared__ uint smx[];
    int s = blockIdx.y;
    const float* B  = (s == 0) ? Wq : (s == 1) ? Wk : Wv;
    const float* bi = (s == 0) ? bq : (s == 1) ? bk : bv;
    float*       C  = (s == 0) ? q  : (s == 1) ? k  : v;
    tgemm_dev<1, 0>(smx, A, B, bi, nullptr, C);
}

// ---------------- GCN aggregate (pre-scaled bf16 rows; dual accumulators) ----------------
__global__ __launch_bounds__(128) void k_gcn_agg(const ushort* __restrict__ hw,
                          const float* __restrict__ hin,
                          const int* __restrict__ rp, const int* __restrict__ col,
                          const float* __restrict__ dis,
                          const float* __restrict__ bc, const float* __restrict__ gn,
                          const float* __restrict__ bn, float* __restrict__ hout,
                          int residual) {
    const int lane = threadIdx.x & 31;
    const int n = blockIdx.x * 4 + (threadIdx.x >> 5);
    const float dn = dis[n];

    uint2 u = *(const uint2*)(hw + (size_t)n * 128 + lane * 4);
    ull a0A = bfp2(u.x), a1A = bfp2(u.y);   // self row (already dis[n]-scaled)
    ull a0B = 0ull,      a1B = 0ull;

    int e = rp[n], end = rp[n + 1];
    for (; e + 8 <= end; e += 8) {
        int   si[8];
        uint2 ui[8];
        #pragma unroll
        for (int q = 0; q < 8; q++) si[q] = __ldg(&col[e + q]);
        #pragma unroll
        for (int q = 0; q < 8; q++) ui[q] = *(const uint2*)(hw + (size_t)si[q] * 128 + lane * 4);
        #pragma unroll
        for (int q = 0; q < 8; q += 2) {
            a0A = add2(a0A, bfp2(ui[q].x));
            a1A = add2(a1A, bfp2(ui[q].y));
            a0B = add2(a0B, bfp2(ui[q + 1].x));
            a1B = add2(a1B, bfp2(ui[q + 1].y));
        }
    }
    for (; e < end; e++) {
        int s = __ldg(&col[e]);
        uint2 u0 = *(const uint2*)(hw + (size_t)s * 128 + lane * 4);
        a0A = add2(a0A, bfp2(u0.x));
        a1A = add2(a1A, bfp2(u0.y));
    }
    ull a0 = add2(a0A, a0B);
    ull a1 = add2(a1A, a1B);

    float x0, x1, x2, x3;
    up2(a0, x0, x1); up2(a1, x2, x3);
    float4 bcv = *(const float4*)&bc[lane * 4];
    x0 = fmaf(dn, x0, bcv.x); x1 = fmaf(dn, x1, bcv.y);
    x2 = fmaf(dn, x2, bcv.z); x3 = fmaf(dn, x3, bcv.w);

    float s  = x0 + x1 + x2 + x3;
    float s2 = x0 * x0 + x1 * x1 + x2 * x2 + x3 * x3;
    #pragma unroll
    for (int o = 16; o > 0; o >>= 1) {
        s  += __shfl_xor_sync(0xffffffffu, s,  o);
        s2 += __shfl_xor_sync(0xffffffffu, s2, o);
    }
    float m   = s  * (1.0f / 128.0f);
    float var = s2 * (1.0f / 128.0f) - m * m;
    float r   = rsqrtf(var + 1e-5f);

    float4 gv = *(const float4*)&gn[lane * 4];
    float4 bv = *(const float4*)&bn[lane * 4];
    float y0 = fmaxf((x0 - m) * r * gv.x + bv.x, 0.0f);
    float y1 = fmaxf((x1 - m) * r * gv.y + bv.y, 0.0f);
    float y2 = fmaxf((x2 - m) * r * gv.z + bv.z, 0.0f);
    float y3 = fmaxf((x3 - m) * r * gv.w + bv.w, 0.0f);
    if (residual) {
        float4 hr = *(const float4*)(hin + (size_t)n * 128 + lane * 4);
        y0 += hr.x; y1 += hr.y; y2 += hr.z; y3 += hr.w;
    }
    *(float4*)(hout + (size_t)n * 128 + lane * 4) = make_float4(y0, y1, y2, y3);
}

// ---------------- tensor-core flash attention ----------------
#define AT_KS 20
#define AT_VS 260
#define AT_PS 36
#define AT_KS_OFF 0
#define AT_VT_OFF (256 * AT_KS)
#define AT_PW_OFF (AT_VT_OFF + 16 * AT_VS)
#define AT_SMEM_W (AT_PW_OFF + 8 * 32 * AT_PS)
#define AT_SMEM_B (AT_SMEM_W * 4)

__global__ __launch_bounds__(256, 3) void k_attn_tc(const float* __restrict__ qg,
                                                    const float* __restrict__ kg,
                                                    const float* __restrict__ vg,
                                                    float* __restrict__ og) {
    extern __shared__ float smf[];
    float* Ks = smf + AT_KS_OFF;
    float* Vt = smf + AT_VT_OFF;
    const int t = threadIdx.x;
    const int lane = t & 31, warp = t >> 5;
    const int gid = lane >> 2, tg = lane & 3;
    float* Pw = smf + AT_PW_OFF + warp * (32 * AT_PS);
    const int g = blockIdx.x >> 3, h = blockIdx.x & 7;
    const size_t base = (size_t)(g * NPG) * 128 + h * 16;
    const float PRE = 0.25f * 1.4426950408889634f;

    {
        const float4* kp = (const float4*)(kg + base + (size_t)t * 128);
        float* kr = Ks + t * AT_KS;
        #pragma unroll
        for (int i = 0; i < 4; i++) {
            float4 v = kp[i];
            kr[i*4+0] = tf32f(v.x); kr[i*4+1] = tf32f(v.y);
            kr[i*4+2] = tf32f(v.z); kr[i*4+3] = tf32f(v.w);
        }
        const float4* vp = (const float4*)(vg + base + (size_t)t * 128);
        #pragma unroll
        for (int i = 0; i < 4; i++) {
            float4 v = vp[i];
            Vt[(i*4+0) * AT_VS + t] = tf32f(v.x);
            Vt[(i*4+1) * AT_VS + t] = tf32f(v.y);
            Vt[(i*4+2) * AT_VS + t] = tf32f(v.z);
            Vt[(i*4+3) * AT_VS + t] = tf32f(v.w);
        }
    }
    const int wm0 = warp * 32;
    float qf[2][8];
    #pragma unroll
    for (int mi = 0; mi < 2; mi++) {
        size_t r0 = (size_t)(g * NPG + wm0 + mi * 16 + gid) * 128 + h * 16;
        size_t r1 = r0 + 8 * 128;
        #pragma unroll
        for (int ks = 0; ks < 2; ks++) {
            qf[mi][ks*4+0] = tf32f(qg[r0 + ks*8 + tg]     * PRE);
            qf[mi][ks*4+1] = tf32f(qg[r1 + ks*8 + tg]     * PRE);
            qf[mi][ks*4+2] = tf32f(qg[r0 + ks*8 + tg + 4] * PRE);
            qf[mi][ks*4+3] = tf32f(qg[r1 + ks*8 + tg + 4] * PRE);
        }
    }
    __syncthreads();

    float oacc[2][2][4];
    float lacc[2][2];
    #pragma unroll
    for (int mi = 0; mi < 2; mi++) {
        lacc[mi][0] = 0.0f; lacc[mi][1] = 0.0f;
        #pragma unroll
        for (int ni = 0; ni < 2; ni++)
            #pragma unroll
            for (int q = 0; q < 4; q++) oacc[mi][ni][q] = 0.0f;
    }

    #pragma unroll 1
    for (int jt = 0; jt < 8; jt++) {
        const int j0 = jt * 32;
        float sacc[2][4][4];
        #pragma unroll
        for (int mi = 0; mi < 2; mi++)
            #pragma unroll
            for (int ni = 0; ni < 4; ni++)
                #pragma unroll
                for (int q = 0; q < 4; q++) sacc[mi][ni][q] = 0.0f;
        #pragma unroll
        for (int ks = 0; ks < 2; ks++) {
            float bf[4][2];
            #pragma unroll
            for (int ni = 0; ni < 4; ni++) {
                const float* kb = &Ks[(j0 + ni * 8 + gid) * AT_KS + ks * 8 + tg];
                bf[ni][0] = kb[0]; bf[ni][1] = kb[4];
            }
            #pragma unroll
            for (int mi = 0; mi < 2; mi++)
                #pragma unroll
                for (int ni = 0; ni < 4; ni++)
                    mmaf(sacc[mi][ni], qf[mi][ks*4+0], qf[mi][ks*4+1],
                         qf[mi][ks*4+2], qf[mi][ks*4+3], bf[ni][0], bf[ni][1]);
        }
        __syncwarp();
        #pragma unroll
        for (int mi = 0; mi < 2; mi++) {
            #pragma unroll
            for (int ni = 0; ni < 4; ni++) {
                float p0 = trunc13(exp2f(fminf(sacc[mi][ni][0], 80.0f)));
                float p1 = trunc13(exp2f(fminf(sacc[mi][ni][1], 80.0f)));
                float p2 = trunc13(exp2f(fminf(sacc[mi][ni][2], 80.0f)));
                float p3 = trunc13(exp2f(fminf(sacc[mi][ni][3], 80.0f)));
                lacc[mi][0] += p0 + p1;
                lacc[mi][1] += p2 + p3;
                int c = ni * 8 + tg * 2;
                *(float2*)&Pw[(mi * 16 + gid) * AT_PS + c]     = make_float2(p0, p1);
                *(float2*)&Pw[(mi * 16 + gid + 8) * AT_PS + c] = make_float2(p2, p3);
            }
        }
        __syncwarp();
        #pragma unroll
        for (int ks = 0; ks < 4; ks++) {
            float vb[2][2];
            #pragma unroll
            for (int ni = 0; ni < 2; ni++) {
                const float* vr = &Vt[(ni * 8 + gid) * AT_VS + j0 + ks * 8 + tg];
                vb[ni][0] = vr[0]; vb[ni][1] = vr[4];
            }
            float af[2][4];
            #pragma unroll
            for (int mi = 0; mi < 2; mi++) {
                const float* p0 = &Pw[(mi * 16 + gid) * AT_PS + ks * 8 + tg];
                const float* p1 = &Pw[(mi * 16 + gid + 8) * AT_PS + ks * 8 + tg];
                af[mi][0] = p0[0]; af[mi][1] = p1[0];
                af[mi][2] = p0[4]; af[mi][3] = p1[4];
            }
            #pragma unroll
            for (int mi = 0; mi < 2; mi++)
                #pragma unroll
                for (int ni = 0; ni < 2; ni++)
                    mmaf(oacc[mi][ni], af[mi][0], af[mi][1], af[mi][2], af[mi][3],
                         vb[ni][0], vb[ni][1]);
        }
        __syncwarp();
    }

    #pragma unroll
    for (int mi = 0; mi < 2; mi++) {
        #pragma unroll
        for (int u = 0; u < 2; u++) {
            float l = lacc[mi][u];
            l += __shfl_xor_sync(0xffffffffu, l, 1);
            l += __shfl_xor_sync(0xffffffffu, l, 2);
            lacc[mi][u] = 1.0f / l;
        }
    }
    #pragma unroll
    for (int mi = 0; mi < 2; mi++) {
        int r0 = g * NPG + wm0 + mi * 16 + gid;
        #pragma unroll
        for (int ni = 0; ni < 2; ni++) {
            int c = h * 16 + ni * 8 + tg * 2;
            *(float2*)&og[(size_t)r0 * 128 + c] =
                make_float2(oacc[mi][ni][0] * lacc[mi][0], oacc[mi][ni][1] * lacc[mi][0]);
            *(float2*)&og[(size_t)(r0 + 8) * 128 + c] =
                make_float2(oacc[mi][ni][2] * lacc[mi][1], oacc[mi][ni][3] * lacc[mi][1]);
        }
    }
}

// ---------------- fused: LN(out_proj + residual) -> pooling -> classifier (+deg cleanup) ----------------
__global__ __launch_bounds__(256) void k_lnpool_cls(const float* __restrict__ o2,
                          const float* __restrict__ hres,
                          const float* __restrict__ ga, const float* __restrict__ ba,
                          const float* __restrict__ W1, const float* __restrict__ b1,
                          const float* __restrict__ g1, const float* __restrict__ beta1,
                          const float* __restrict__ W2, const float* __restrict__ b2,
                          const float* __restrict__ W3, const float* __restrict__ b3,
                          float* __restrict__ out, int* __restrict__ deg) {
    if (blockIdx.x >= GG) {
        deg[(blockIdx.x - GG) * 256 + threadIdx.x] = 0;
        return;
    }
    __shared__ float ssum[8][128];
    __shared__ float smax[8][128];
    __shared__ float ps[384];
    __shared__ float z1[128];
    __shared__ float z2[64];
    __shared__ float red[8];
    const int g = blockIdx.x;
    const int w = threadIdx.x >> 5, lane = threadIdx.x & 31;
    {
        float4 gv = *(const float4*)&ga[lane * 4];
        float4 bv = *(const float4*)&ba[lane * 4];
        float4 psum = make_float4(0.f, 0.f, 0.f, 0.f);
        float4 pm = make_float4(-1e30f, -1e30f, -1e30f, -1e30f);
        #pragma unroll 2
        for (int i = 0; i < 32; i++) {
            size_t n = (size_t)g * NPG + w * 32 + i;
            float4 a = *(const float4*)(o2   + n * 128 + lane * 4);
            float4 b = *(const float4*)(hres + n * 128 + lane * 4);
            float x0 = a.x + b.x, x1 = a.y + b.y, x2 = a.z + b.z, x3 = a.w + b.w;
            float s  = x0 + x1 + x2 + x3;
            float s2 = x0*x0 + x1*x1 + x2*x2 + x3*x3;
            #pragma unroll
            for (int o = 16; o > 0; o >>= 1) {
                s  += __shfl_xor_sync(0xffffffffu, s,  o);
                s2 += __shfl_xor_sync(0xffffffffu, s2, o);
            }
            float m   = s  * (1.0f / 128.0f);
            float var = s2 * (1.0f / 128.0f) - m * m;
            float r   = rsqrtf(var + 1e-5f);
            float y0 = (x0 - m) * r * gv.x + bv.x;
            float y1 = (x1 - m) * r * gv.y + bv.y;
            float y2 = (x2 - m) * r * gv.z + bv.z;
            float y3 = (x3 - m) * r * gv.w + bv.w;
            psum.x += y0; psum.y += y1; psum.z += y2; psum.w += y3;
            pm.x = fmaxf(pm.x, y0); pm.y = fmaxf(pm.y, y1);
            pm.z = fmaxf(pm.z, y2); pm.w = fmaxf(pm.w, y3);
        }
        *(float4*)&ssum[w][lane * 4] = psum;
        *(float4*)&smax[w][lane * 4] = pm;
    }
    __syncthreads();
    {
        int f = threadIdx.x;
        if (f < 128) {
            float s = ssum[0][f], mx = smax[0][f];
            #pragma unroll
            for (int ww = 1; ww < 8; ww++) {
                s += ssum[ww][f];
                mx = fmaxf(mx, smax[ww][f]);
            }
            ps[f]       = s * (1.0f / 256.0f);
            ps[128 + f] = mx;
            ps[256 + f] = s;
        }
    }
    __syncthreads();
    const int f = threadIdx.x;
    float acc = 0.0f;
    if (f < 128) {
        acc = b1[f];
        for (int k = 0; k < 384; k++) acc = fmaf(ps[k], W1[k * 128 + f], acc);
    }
    {
        float s = (f < 128) ? acc : 0.0f;
        float s2 = s * s;
        #pragma unroll
        for (int o = 16; o > 0; o >>= 1) {
            s  += __shfl_xor_sync(0xffffffffu, s,  o);
            s2 += __shfl_xor_sync(0xffffffffu, s2, o);
        }
        if (w < 4 && lane == 0) { red[w] = s; red[4 + w] = s2; }
        __syncthreads();
        if (f < 128) {
            float ts  = red[0] + red[1] + red[2] + red[3];
            float ts2 = red[4] + red[5] + red[6] + red[7];
            float m   = ts  * (1.0f / 128.0f);
            float var = ts2 * (1.0f / 128.0f) - m * m;
            float r   = rsqrtf(var + 1e-5f);
            z1[f] = fmaxf((acc - m) * r * g1[f] + beta1[f], 0.0f);
        }
    }
    __syncthreads();
    if (f < 64) {
        float a = b2[f];
        #pragma unroll 8
        for (int k = 0; k < 128; k++) a = fmaf(z1[k], W2[k * 64 + f], a);
        z2[f] = fmaxf(a, 0.0f);
    }
    __syncthreads();
    if (f < 2) {
        float a = b3[f];
        #pragma unroll
        for (int k = 0; k < 64; k++) a = fmaf(z2[k], W3[k * 2 + f], a);
        out[g * 2 + f] = a;
    }
}

// ---------------- launch ----------------
extern "C" void kernel_launch(void* const* d_in, const int* in_sizes, int n_in,
                              void* d_out, int out_size) {
    const float* x     = (const float*)d_in[0];
    const int*   ei    = (const int*)  d_in[1];
    const float* W_in  = (const float*)d_in[3];
    const float* b_in  = (const float*)d_in[4];
    const float* g_in  = (const float*)d_in[5];
    const float* be_in = (const float*)d_in[6];
    const float* Wc    = (const float*)d_in[7];
    const float* bc    = (const float*)d_in[8];
    const float* gn    = (const float*)d_in[9];
    const float* bn    = (const float*)d_in[10];
    const float* Wq    = (const float*)d_in[11];
    const float* bq    = (const float*)d_in[12];
    const float* Wk    = (const float*)d_in[13];
    const float* bk    = (const float*)d_in[14];
    const float* Wv    = (const float*)d_in[15];
    const float* bv    = (const float*)d_in[16];
    const float* Wo    = (const float*)d_in[17];
    const float* bo    = (const float*)d_in[18];
    const float* ga    = (const float*)d_in[19];
    const float* ba    = (const float*)d_in[20];
    const float* W1    = (const float*)d_in[21];
    const float* b1    = (const float*)d_in[22];
    const float* g1    = (const float*)d_in[23];
    const float* beta1 = (const float*)d_in[24];
    const float* W2    = (const float*)d_in[25];
    const float* b2    = (const float*)d_in[26];
    const float* W3    = (const float*)d_in[27];
    const float* b3    = (const float*)d_in[28];
    float* out = (float*)d_out;

    const int* src = ei;
    const int* dst = ei + EE;

    float *p_h, *p_h2, *p_tmp, *p_q, *p_k, *p_v, *p_dis, *p_wct;
    ushort *p_hwbf;
    int *p_deg, *p_rp, *p_cur, *p_col, *p_done;
    cudaGetSymbolAddress((void**)&p_h,    g_h);
    cudaGetSymbolAddress((void**)&p_h2,   g_h2);
    cudaGetSymbolAddress((void**)&p_tmp,  g_tmp);
    cudaGetSymbolAddress((void**)&p_q,    g_q);
    cudaGetSymbolAddress((void**)&p_k,    g_k);
    cudaGetSymbolAddress((void**)&p_v,    g_v);
    cudaGetSymbolAddress((void**)&p_hwbf, g_hwbf);
    cudaGetSymbolAddress((void**)&p_wct,  g_wct);
    cudaGetSymbolAddress((void**)&p_deg,  g_deg);
    cudaGetSymbolAddress((void**)&p_rp,   g_rp);
    cudaGetSymbolAddress((void**)&p_cur,  g_cur);
    cudaGetSymbolAddress((void**)&p_col,  g_col);
    cudaGetSymbolAddress((void**)&p_dis,  g_dis);
    cudaGetSymbolAddress((void**)&p_done, g_done);

    const int HS = 6 * STG_W * sizeof(uint);   // 98304 B (3 stages x (A+B))
    cudaFuncSetAttribute(k_tgemm<0, 1>, cudaFuncAttributeMaxDynamicSharedMemorySize, HS);
    cudaFuncSetAttribute(k_tgemm<1, 0>, cudaFuncAttributeMaxDynamicSharedMemorySize, HS);
    cudaFuncSetAttribute(k_tgemm_qkv,   cudaFuncAttributeMaxDynamicSharedMemorySize, HS);
    cudaFuncSetAttribute(k_attn_tc,     cudaFuncAttributeMaxDynamicSharedMemorySize, AT_SMEM_B);

    // (1) hist+scan+wt  (2) fill+proj  (3) tgemm L1  (4) agg <- profiled
    k_histscan_wt<<<1024 + 48, 256>>>(dst, p_deg, p_rp, p_cur, p_dis, p_done, Wc, p_wct);
    k_fill_proj<<<1024 + 512, 256>>>(src, dst, p_cur, p_col,
                                     x, W_in, b_in, g_in, be_in, p_h);
    k_tgemm<0, 1><<<NN / 128, 256, HS>>>(p_h, p_wct, nullptr, p_dis, p_hwbf);
    k_gcn_agg<<<NN / 4, 128>>>(p_hwbf, p_h, p_rp, p_col, p_dis, bc, gn, bn, p_h2, 0);

    float* cur = p_h2;
    float* nxt = p_h;
    for (int i = 1; i < NLAYERS; i++) {
        k_tgemm<0, 1><<<NN / 128, 256, HS>>>(cur, p_wct + i * HID * HID, nullptr, p_dis, p_hwbf);
        k_gcn_agg<<<NN / 4, 128>>>(p_hwbf, cur, p_rp, p_col, p_dis,
                                   bc + i * HID, gn + i * HID, bn + i * HID, nxt, 1);
        float* t = cur; cur = nxt; nxt = t;
    }
    // cur == p_h2

    {
        dim3 grid(NN / 128, 3);
        k_tgemm_qkv<<<grid, 256, HS>>>(cur, Wq, bq, p_q, Wk, bk, p_k, Wv, bv, p_v);
    }
    k_attn_tc<<<GG * NH, 256, AT_SMEM_B>>>(p_q, p_k, p_v, p_tmp);
    k_tgemm<1, 0><<<NN / 128, 256, HS>>>(p_tmp, Wo, bo, nullptr, p_q);

    k_lnpool_cls<<<GG + 128, 256>>>(p_q, cur, ga, ba, W1, b1, g1, beta1,
                                    W2, b2, W3, b3, out, p_deg);
}

// round 15
// speedup vs baseline: 1.0344x; 1.0344x over previous
#include <cuda_runtime.h>
#include <math.h>

#define NN      32768      // nodes
#define GG      128        // graphs
#define NPG     256        // nodes per graph
#define HID     128
#define NH      8
#define DH      16
#define EE      1048576    // edges
#define NLAYERS 3

typedef unsigned long long ull;
typedef unsigned int uint;
typedef unsigned short ushort;

// ---------------- packed f32x2 helpers ----------------
__device__ __forceinline__ ull pk2(float lo, float hi) {
    ull r; asm("mov.b64 %0,{%1,%2};" : "=l"(r) : "f"(lo), "f"(hi)); return r;
}
__device__ __forceinline__ void up2(ull v, float& lo, float& hi) {
    asm("mov.b64 {%0,%1},%2;" : "=f"(lo), "=f"(hi) : "l"(v));
}
__device__ __forceinline__ ull add2(ull a, ull b) {
    ull d; asm("add.rn.f32x2 %0,%1,%2;" : "=l"(d) : "l"(a), "l"(b)); return d;
}
__device__ __forceinline__ uint bf2(float lo, float hi) {
    uint r; asm("cvt.rn.bf16x2.f32 %0,%1,%2;" : "=r"(r) : "f"(hi), "f"(lo)); return r;
}
// bf16x2 word -> packed f32x2 (ull): lo half -> low float, hi half -> high float
__device__ __forceinline__ ull bfp2(uint u) {
    return ((ull)(u & 0xffff0000u) << 32) | ((ull)(u << 16));
}
__device__ __forceinline__ uint tf32(float x) {
    uint r; asm("cvt.rna.tf32.f32 %0,%1;" : "=r"(r) : "f"(x)); return r;
}
__device__ __forceinline__ float tf32f(float x) { return __uint_as_float(tf32(x)); }
__device__ __forceinline__ float trunc13(float x) {
    return __uint_as_float(__float_as_uint(x) & 0xffffe000u);
}
__device__ __forceinline__ void mma1688(float* c, uint a0, uint a1, uint a2, uint a3,
                                        uint b0, uint b1) {
    asm volatile("mma.sync.aligned.m16n8k8.row.col.f32.tf32.tf32.f32 "
        "{%0,%1,%2,%3},{%4,%5,%6,%7},{%8,%9},{%0,%1,%2,%3};"
        : "+f"(c[0]), "+f"(c[1]), "+f"(c[2]), "+f"(c[3])
        : "r"(a0), "r"(a1), "r"(a2), "r"(a3), "r"(b0), "r"(b1));
}
__device__ __forceinline__ void mmaf(float* c, float a0, float a1, float a2, float a3,
                                     float b0, float b1) {
    mma1688(c, __float_as_uint(a0), __float_as_uint(a1), __float_as_uint(a2),
            __float_as_uint(a3), __float_as_uint(b0), __float_as_uint(b1));
}
__device__ __forceinline__ void cpa16(uint dst, const void* src) {
    asm volatile("cp.async.ca.shared.global [%0], [%1], 16;" :: "r"(dst), "l"(src));
}
#define CP_COMMIT() asm volatile("cp.async.commit_group;" ::: "memory")
#define CP_WAIT(N)  asm volatile("cp.async.wait_group %0;" :: "n"(N) : "memory")

// ---------------- scratch (device globals; zero-initialized at module load) ----------------
__device__ float  g_h   [NN * HID];
__device__ float  g_h2  [NN * HID];
__device__ float  g_tmp [NN * HID];
__device__ float  g_q   [NN * HID];
__device__ float  g_k   [NN * HID];
__device__ float  g_v   [NN * HID];
__device__ ushort g_hwbf[NN * HID];
__device__ float  g_wct [NLAYERS * HID * HID];
__device__ int    g_deg[NN];        // zero at invocation start (cleanup re-zeros)
__device__ int    g_rp [NN + 1];
__device__ int    g_cur[NN];
__device__ int    g_col[EE];        // stores BYTE offsets (src_node * 256)
__device__ float  g_dis[NN];
__device__ int    g_done[1];

// ---------------- kernel 1: hist + scan (last-block) + weight transpose ----------------
__global__ __launch_bounds__(256) void k_histscan_wt(const int* __restrict__ dst,
                        int* __restrict__ deg, int* __restrict__ rp,
                        int* __restrict__ cur, float* __restrict__ dis,
                        int* __restrict__ done,
                        const float* __restrict__ Wc, float* __restrict__ WT) {
    if (blockIdx.x >= 1024) {
        int w = (blockIdx.x - 1024) * 8 + (threadIdx.x >> 5);   // 0..383
        int l = w >> 7, f = w & 127;
        int lane = threadIdx.x & 31;
        const float* Wl = Wc + l * 16384;
        float4 v;
        v.x = __ldg(&Wl[(lane * 4 + 0) * 128 + f]);
        v.y = __ldg(&Wl[(lane * 4 + 1) * 128 + f]);
        v.z = __ldg(&Wl[(lane * 4 + 2) * 128 + f]);
        v.w = __ldg(&Wl[(lane * 4 + 3) * 128 + f]);
        *(float4*)&WT[(size_t)l * 16384 + f * 128 + lane * 4] = v;
        return;
    }
    int e = (blockIdx.x * 256 + threadIdx.x) * 4;
    int4 d = *(const int4*)&dst[e];
    atomicAdd(&deg[d.x], 1);
    atomicAdd(&deg[d.y], 1);
    atomicAdd(&deg[d.z], 1);
    atomicAdd(&deg[d.w], 1);
    __threadfence();
    __shared__ int amLast;
    if (threadIdx.x == 0)
        amLast = (atomicAdd(done, 1) == 1023);
    __syncthreads();
    if (!amLast) return;

    __shared__ int part[256];
    const int tid = threadIdx.x;
    const int base = tid * 128;
    int s = 0;
    for (int i = 0; i < 128; i++) s += deg[base + i];
    part[tid] = s;
    __syncthreads();
    for (int off = 1; off < 256; off <<= 1) {
        int t = (tid >= off) ? part[tid - off] : 0;
        __syncthreads();
        part[tid] += t;
        __syncthreads();
    }
    int run = part[tid] - s;
    for (int i = 0; i < 128; i++) {
        int d0 = deg[base + i];
        rp[base + i]  = run;
        cur[base + i] = run;
        dis[base + i] = rsqrtf((float)d0 + 1.0f);
        run += d0;
    }
    if (tid == 255) rp[NN] = run;
    if (tid == 0) *done = 0;
}

// ---------------- kernel 2: CSR fill (byte offsets) + input projection ----------------
__global__ __launch_bounds__(256) void k_fill_proj(const int* __restrict__ src,
                       const int* __restrict__ dst,
                       int* __restrict__ cur, int* __restrict__ col,
                       const float* __restrict__ x, const float* __restrict__ W,
                       const float* __restrict__ b, const float* __restrict__ g,
                       const float* __restrict__ be, float* __restrict__ out) {
    if (blockIdx.x < 1024) {
        int e = (blockIdx.x * 256 + threadIdx.x) * 4;
        int4 s = *(const int4*)&src[e];
        int4 d = *(const int4*)&dst[e];
        int p0 = atomicAdd(&cur[d.x], 1);
        int p1 = atomicAdd(&cur[d.y], 1);
        int p2 = atomicAdd(&cur[d.z], 1);
        int p3 = atomicAdd(&cur[d.w], 1);
        // store BYTE offset of the bf16 row: node * 128 * 2
        col[p0] = s.x << 8; col[p1] = s.y << 8;
        col[p2] = s.z << 8; col[p3] = s.w << 8;
        return;
    }
    const int lane = threadIdx.x & 31;
    const int n0 = ((blockIdx.x - 1024) * 8 + (threadIdx.x >> 5)) * 8;
    float4 w[15];
    #pragma unroll
    for (int k = 0; k < 15; k++) w[k] = *(const float4*)&W[k * 128 + lane * 4];
    const float4 bb = *(const float4*)&b[lane * 4];
    const float4 gv = *(const float4*)&g[lane * 4];
    const float4 bv = *(const float4*)&be[lane * 4];
    float4 xv = make_float4(0.f, 0.f, 0.f, 0.f);
    if (lane < 30) xv = *(const float4*)&x[n0 * 15 + lane * 4];

    #pragma unroll
    for (int i = 0; i < 8; i++) {
        float4 acc = bb;
        #pragma unroll
        for (int k = 0; k < 15; k++) {
            const int e = i * 15 + k;
            const int srcLane = e >> 2, comp = e & 3;
            float xe = (comp == 0) ? xv.x : (comp == 1) ? xv.y : (comp == 2) ? xv.z : xv.w;
            float xk = __shfl_sync(0xffffffffu, xe, srcLane);
            acc.x = fmaf(xk, w[k].x, acc.x); acc.y = fmaf(xk, w[k].y, acc.y);
            acc.z = fmaf(xk, w[k].z, acc.z); acc.w = fmaf(xk, w[k].w, acc.w);
        }
        float s  = acc.x + acc.y + acc.z + acc.w;
        float s2 = acc.x*acc.x + acc.y*acc.y + acc.z*acc.z + acc.w*acc.w;
        #pragma unroll
        for (int o = 16; o > 0; o >>= 1) {
            s  += __shfl_xor_sync(0xffffffffu, s,  o);
            s2 += __shfl_xor_sync(0xffffffffu, s2, o);
        }
        float m   = s * (1.0f / 128.0f);
        float var = s2 * (1.0f / 128.0f) - m * m;
        float r   = rsqrtf(var + 1e-5f);
        float4 y;
        y.x = fmaxf((acc.x - m) * r * gv.x + bv.x, 0.0f);
        y.y = fmaxf((acc.y - m) * r * gv.y + bv.y, 0.0f);
        y.z = fmaxf((acc.z - m) * r * gv.z + bv.z, 0.0f);
        y.w = fmaxf((acc.w - m) * r * gv.w + bv.w, 0.0f);
        *(float4*)(out + (size_t)(n0 + i) * 128 + lane * 4) = y;
    }
}

// ---------------- tf32 tensor-core GEMM (2-stage cp.async; R13 config) ----------------
#define STG_W 4096

__device__ __forceinline__ void stage_issue(uint smA, uint smB,
                                            const float* __restrict__ A,
                                            const float* __restrict__ B,
                                            int row0, int kt, int t) {
    #pragma unroll
    for (int i = 0; i < 4; i++) {
        int idx = i * 256 + t;
        int r = idx >> 3, c4 = (idx & 7) * 4;
        int cs = c4 ^ ((r & 7) << 2);
        cpa16(smA + (uint)(r * 32 + cs) * 4u, &A[(size_t)(row0 + r) * 128 + kt * 32 + c4]);
    }
    #pragma unroll
    for (int i = 0; i < 4; i++) {
        int idx = i * 256 + t;
        int r = idx >> 3, c4 = (idx & 7) * 4;
        int cs = c4 ^ ((r & 7) << 2);
        cpa16(smB + (uint)(r * 32 + cs) * 4u, &B[(size_t)r * 128 + kt * 32 + c4]);
    }
}

template <int BIAS, int BF16OUT>
__device__ __forceinline__ void tgemm_dev(uint* sm, const float* __restrict__ A,
                                          const float* __restrict__ B,
                                          const float* __restrict__ bias,
                                          const float* __restrict__ dis,
                                          void* __restrict__ Cv) {
    const int t = threadIdx.x;
    const int lane = t & 31, warp = t >> 5;
    const int row0 = blockIdx.x * 128;
    const int m0 = (warp >> 2) * 64;
    const int n0 = (warp & 3) * 32;
    const int gid = lane >> 2, tg = lane & 3;
    const uint smbase = (uint)__cvta_generic_to_shared(sm);

    stage_issue(smbase, smbase + STG_W * 4u, A, B, row0, 0, t);
    CP_COMMIT();
    stage_issue(smbase + 2u * STG_W * 4u, smbase + 3u * STG_W * 4u, A, B, row0, 1, t);
    CP_COMMIT();

    float acc[4][4][4];
    #pragma unroll
    for (int mi = 0; mi < 4; mi++)
        #pragma unroll
        for (int ni = 0; ni < 4; ni++)
            #pragma unroll
            for (int q = 0; q < 4; q++) acc[mi][ni][q] = 0.0f;

    #pragma unroll
    for (int kt = 0; kt < 4; kt++) {
        if (kt < 3) { CP_WAIT(1); } else { CP_WAIT(0); }
        __syncthreads();
        const uint* As = sm + (kt & 1) * 2 * STG_W;
        const uint* Bs = As + STG_W;
        #pragma unroll
        for (int ks = 0; ks < 4; ks++) {
            const int c0 = (ks * 8 + tg) ^ (gid << 2);
            const int c1 = c0 ^ 4;
            uint af[4][4];
            #pragma unroll
            for (int mi = 0; mi < 4; mi++) {
                const uint* a0 = &As[(m0 + mi * 16 + gid) * 32];
                const uint* a1 = &As[(m0 + mi * 16 + gid + 8) * 32];
                af[mi][0] = a0[c0]; af[mi][1] = a1[c0];
                af[mi][2] = a0[c1]; af[mi][3] = a1[c1];
            }
            uint bf[4][2];
            #pragma unroll
            for (int ni = 0; ni < 4; ni++) {
                const uint* b0 = &Bs[(n0 + ni * 8 + gid) * 32];
                bf[ni][0] = b0[c0]; bf[ni][1] = b0[c1];
            }
            #pragma unroll
            for (int mi = 0; mi < 4; mi++)
                #pragma unroll
                for (int ni = 0; ni < 4; ni++)
                    mma1688(acc[mi][ni], af[mi][0], af[mi][1], af[mi][2], af[mi][3],
                            bf[ni][0], bf[ni][1]);
        }
        __syncthreads();
        if (kt < 2) {
            int s = kt + 2;
            uint ab = smbase + (uint)(s & 1) * 2u * STG_W * 4u;
            stage_issue(ab, ab + STG_W * 4u, A, B, row0, s, t);
            CP_COMMIT();
        }
    }

    float2 bb[4];
    #pragma unroll
    for (int ni = 0; ni < 4; ni++) {
        if (BIAS) bb[ni] = *(const float2*)&bias[n0 + ni * 8 + tg * 2];
        else      bb[ni] = make_float2(0.f, 0.f);
    }
    #pragma unroll
    for (int mi = 0; mi < 4; mi++) {
        int r = row0 + m0 + mi * 16 + gid;
        float d0 = 1.0f, d1 = 1.0f;
        if (BF16OUT) { d0 = __ldg(&dis[r]); d1 = __ldg(&dis[r + 8]); }
        #pragma unroll
        for (int ni = 0; ni < 4; ni++) {
            int c = n0 + ni * 8 + tg * 2;
            float v0 = acc[mi][ni][0] + bb[ni].x;
            float v1 = acc[mi][ni][1] + bb[ni].y;
            float v2 = acc[mi][ni][2] + bb[ni].x;
            float v3 = acc[mi][ni][3] + bb[ni].y;
            if (BF16OUT) {
                ushort* Cb = (ushort*)Cv;
                *(uint*)(Cb + (size_t)r * 128 + c)       = bf2(v0 * d0, v1 * d0);
                *(uint*)(Cb + (size_t)(r + 8) * 128 + c) = bf2(v2 * d1, v3 * d1);
            } else {
                float* C = (float*)Cv;
                *(float2*)&C[(size_t)r * 128 + c]       = make_float2(v0, v1);
                *(float2*)&C[(size_t)(r + 8) * 128 + c] = make_float2(v2, v3);
            }
        }
    }
}

template <int BIAS, int BF16OUT>
__global__ __launch_bounds__(256, 2) void k_tgemm(const float* __restrict__ A,
                                                  const float* __restrict__ B,
                                                  const float* __restrict__ bias,
                                                  const float* __restrict__ dis,
                                                  void* __restrict__ C) {
    extern __shared__ uint smx[];
    tgemm_dev<BIAS, BF16OUT>(smx, A, B, bias, dis, C);
}

__global__ __launch_bounds__(256, 2) void k_tgemm_qkv(const float* __restrict__ A,
    const float* __restrict__ Wq, const float* __restrict__ bq, float* __restrict__ q,
    const float* __restrict__ Wk, const float* __restrict__ bk, float* __restrict__ k,
    const float* __restrict__ Wv, const float* __restrict__ bv, float* __restrict__ v) {
    extern __shared__ uint smx[];
    int s = blockIdx.y;
    const float* B  = (s == 0) ? Wq : (s == 1) ? Wk : Wv;
    const float* bi = (s == 0) ? bq : (s == 1) ? bk : bv;
    float*       C  = (s == 0) ? q  : (s == 1) ? k  : v;
    tgemm_dev<1, 0>(smx, A, B, bi, nullptr, C);
}

// ---------------- GCN aggregate (pre-scaled bf16 rows; byte-offset col) ----------------
__global__ __launch_bounds__(128) void k_gcn_agg(const ushort* __restrict__ hw,
                          const float* __restrict__ hin,
                          const int* __restrict__ rp, const int* __restrict__ col,
                          const float* __restrict__ dis,
                          const float* __restrict__ bc, const float* __restrict__ gn,
                          const float* __restrict__ bn, float* __restrict__ hout,
                          int residual) {
    const int lane = threadIdx.x & 31;
    const int n = blockIdx.x * 4 + (threadIdx.x >> 5);
    const float dn = dis[n];
    const char* hwb = (const char*)hw + lane * 8;   // lane-local base

    uint2 u = *(const uint2*)(hwb + ((size_t)n << 8));
    ull a0 = bfp2(u.x), a1 = bfp2(u.y);   // self row (already dis[n]-scaled)

    int e = rp[n], end = rp[n + 1];
    for (; e + 8 <= end; e += 8) {
        int   off[8];
        uint2 ui[8];
        #pragma unroll
        for (int q = 0; q < 8; q++) off[q] = __ldg(&col[e + q]);
        #pragma unroll
        for (int q = 0; q < 8; q++) ui[q] = *(const uint2*)(hwb + off[q]);
        #pragma unroll
        for (int q = 0; q < 8; q++) {
            a0 = add2(a0, bfp2(ui[q].x));
            a1 = add2(a1, bfp2(ui[q].y));
        }
    }
    for (; e < end; e++) {
        int off = __ldg(&col[e]);
        uint2 u0 = *(const uint2*)(hwb + off);
        a0 = add2(a0, bfp2(u0.x));
        a1 = add2(a1, bfp2(u0.y));
    }

    float x0, x1, x2, x3;
    up2(a0, x0, x1); up2(a1, x2, x3);
    float4 bcv = *(const float4*)&bc[lane * 4];
    x0 = fmaf(dn, x0, bcv.x); x1 = fmaf(dn, x1, bcv.y);
    x2 = fmaf(dn, x2, bcv.z); x3 = fmaf(dn, x3, bcv.w);

    float s  = x0 + x1 + x2 + x3;
    float s2 = x0 * x0 + x1 * x1 + x2 * x2 + x3 * x3;
    #pragma unroll
    for (int o = 16; o > 0; o >>= 1) {
        s  += __shfl_xor_sync(0xffffffffu, s,  o);
        s2 += __shfl_xor_sync(0xffffffffu, s2, o);
    }
    float m   = s  * (1.0f / 128.0f);
    float var = s2 * (1.0f / 128.0f) - m * m;
    float r   = rsqrtf(var + 1e-5f);

    float4 gv = *(const float4*)&gn[lane * 4];
    float4 bv = *(const float4*)&bn[lane * 4];
    float y0 = fmaxf((x0 - m) * r * gv.x + bv.x, 0.0f);
    float y1 = fmaxf((x1 - m) * r * gv.y + bv.y, 0.0f);
    float y2 = fmaxf((x2 - m) * r * gv.z + bv.z, 0.0f);
    float y3 = fmaxf((x3 - m) * r * gv.w + bv.w, 0.0f);
    if (residual) {
        float4 hr = *(const float4*)(hin + (size_t)n * 128 + lane * 4);
        y0 += hr.x; y1 += hr.y; y2 += hr.z; y3 += hr.w;
    }
    *(float4*)(hout + (size_t)n * 128 + lane * 4) = make_float4(y0, y1, y2, y3);
}

// ---------------- tensor-core flash attention (R13 config: occ 2) ----------------
#define AT_KS 20
#define AT_VS 260
#define AT_PS 36
#define AT_KS_OFF 0
#define AT_VT_OFF (256 * AT_KS)
#define AT_PW_OFF (AT_VT_OFF + 16 * AT_VS)
#define AT_SMEM_W (AT_PW_OFF + 8 * 32 * AT_PS)
#define AT_SMEM_B (AT_SMEM_W * 4)

__global__ __launch_bounds__(256, 2) void k_attn_tc(const float* __restrict__ qg,
                                                    const float* __restrict__ kg,
                                                    const float* __restrict__ vg,
                                                    float* __restrict__ og) {
    extern __shared__ float smf[];
    float* Ks = smf + AT_KS_OFF;
    float* Vt = smf + AT_VT_OFF;
    const int t = threadIdx.x;
    const int lane = t & 31, warp = t >> 5;
    const int gid = lane >> 2, tg = lane & 3;
    float* Pw = smf + AT_PW_OFF + warp * (32 * AT_PS);
    const int g = blockIdx.x >> 3, h = blockIdx.x & 7;
    const size_t base = (size_t)(g * NPG) * 128 + h * 16;
    const float PRE = 0.25f * 1.4426950408889634f;

    {
        const float4* kp = (const float4*)(kg + base + (size_t)t * 128);
        float* kr = Ks + t * AT_KS;
        #pragma unroll
        for (int i = 0; i < 4; i++) {
            float4 v = kp[i];
            kr[i*4+0] = tf32f(v.x); kr[i*4+1] = tf32f(v.y);
            kr[i*4+2] = tf32f(v.z); kr[i*4+3] = tf32f(v.w);
        }
        const float4* vp = (const float4*)(vg + base + (size_t)t * 128);
        #pragma unroll
        for (int i = 0; i < 4; i++) {
            float4 v = vp[i];
            Vt[(i*4+0) * AT_VS + t] = tf32f(v.x);
            Vt[(i*4+1) * AT_VS + t] = tf32f(v.y);
            Vt[(i*4+2) * AT_VS + t] = tf32f(v.z);
            Vt[(i*4+3) * AT_VS + t] = tf32f(v.w);
        }
    }
    const int wm0 = warp * 32;
    float qf[2][8];
    #pragma unroll
    for (int mi = 0; mi < 2; mi++) {
        size_t r0 = (size_t)(g * NPG + wm0 + mi * 16 + gid) * 128 + h * 16;
        size_t r1 = r0 + 8 * 128;
        #pragma unroll
        for (int ks = 0; ks < 2; ks++) {
            qf[mi][ks*4+0] = tf32f(qg[r0 + ks*8 + tg]     * PRE);
            qf[mi][ks*4+1] = tf32f(qg[r1 + ks*8 + tg]     * PRE);
            qf[mi][ks*4+2] = tf32f(qg[r0 + ks*8 + tg + 4] * PRE);
            qf[mi][ks*4+3] = tf32f(qg[r1 + ks*8 + tg + 4] * PRE);
        }
    }
    __syncthreads();

    float oacc[2][2][4];
    float lacc[2][2];
    #pragma unroll
    for (int mi = 0; mi < 2; mi++) {
        lacc[mi][0] = 0.0f; lacc[mi][1] = 0.0f;
        #pragma unroll
        for (int ni = 0; ni < 2; ni++)
            #pragma unroll
            for (int q = 0; q < 4; q++) oacc[mi][ni][q] = 0.0f;
    }

    #pragma unroll 1
    for (int jt = 0; jt < 8; jt++) {
        const int j0 = jt * 32;
        float sacc[2][4][4];
        #pragma unroll
        for (int mi = 0; mi < 2; mi++)
            #pragma unroll
            for (int ni = 0; ni < 4; ni++)
                #pragma unroll
                for (int q = 0; q < 4; q++) sacc[mi][ni][q] = 0.0f;
        #pragma unroll
        for (int ks = 0; ks < 2; ks++) {
            float bf[4][2];
            #pragma unroll
            for (int ni = 0; ni < 4; ni++) {
                const float* kb = &Ks[(j0 + ni * 8 + gid) * AT_KS + ks * 8 + tg];
                bf[ni][0] = kb[0]; bf[ni][1] = kb[4];
            }
            #pragma unroll
            for (int mi = 0; mi < 2; mi++)
                #pragma unroll
                for (int ni = 0; ni < 4; ni++)
                    mmaf(sacc[mi][ni], qf[mi][ks*4+0], qf[mi][ks*4+1],
                         qf[mi][ks*4+2], qf[mi][ks*4+3], bf[ni][0], bf[ni][1]);
        }
        __syncwarp();
        #pragma unroll
        for (int mi = 0; mi < 2; mi++) {
            #pragma unroll
            for (int ni = 0; ni < 4; ni++) {
                float p0 = trunc13(exp2f(fminf(sacc[mi][ni][0], 80.0f)));
                float p1 = trunc13(exp2f(fminf(sacc[mi][ni][1], 80.0f)));
                float p2 = trunc13(exp2f(fminf(sacc[mi][ni][2], 80.0f)));
                float p3 = trunc13(exp2f(fminf(sacc[mi][ni][3], 80.0f)));
                lacc[mi][0] += p0 + p1;
                lacc[mi][1] += p2 + p3;
                int c = ni * 8 + tg * 2;
                *(float2*)&Pw[(mi * 16 + gid) * AT_PS + c]     = make_float2(p0, p1);
                *(float2*)&Pw[(mi * 16 + gid + 8) * AT_PS + c] = make_float2(p2, p3);
            }
        }
        __syncwarp();
        #pragma unroll
        for (int ks = 0; ks < 4; ks++) {
            float vb[2][2];
            #pragma unroll
            for (int ni = 0; ni < 2; ni++) {
                const float* vr = &Vt[(ni * 8 + gid) * AT_VS + j0 + ks * 8 + tg];
                vb[ni][0] = vr[0]; vb[ni][1] = vr[4];
            }
            float af[2][4];
            #pragma unroll
            for (int mi = 0; mi < 2; mi++) {
                const float* p0 = &Pw[(mi * 16 + gid) * AT_PS + ks * 8 + tg];
                const float* p1 = &Pw[(mi * 16 + gid + 8) * AT_PS + ks * 8 + tg];
                af[mi][0] = p0[0]; af[mi][1] = p1[0];
                af[mi][2] = p0[4]; af[mi][3] = p1[4];
            }
            #pragma unroll
            for (int mi = 0; mi < 2; mi++)
                #pragma unroll
                for (int ni = 0; ni < 2; ni++)
                    mmaf(oacc[mi][ni], af[mi][0], af[mi][1], af[mi][2], af[mi][3],
                         vb[ni][0], vb[ni][1]);
        }
        __syncwarp();
    }

    #pragma unroll
    for (int mi = 0; mi < 2; mi++) {
        #pragma unroll
        for (int u = 0; u < 2; u++) {
            float l = lacc[mi][u];
            l += __shfl_xor_sync(0xffffffffu, l, 1);
            l += __shfl_xor_sync(0xffffffffu, l, 2);
            lacc[mi][u] = 1.0f / l;
        }
    }
    #pragma unroll
    for (int mi = 0; mi < 2; mi++) {
        int r0 = g * NPG + wm0 + mi * 16 + gid;
        #pragma unroll
        for (int ni = 0; ni < 2; ni++) {
            int c = h * 16 + ni * 8 + tg * 2;
            *(float2*)&og[(size_t)r0 * 128 + c] =
                make_float2(oacc[mi][ni][0] * lacc[mi][0], oacc[mi][ni][1] * lacc[mi][0]);
            *(float2*)&og[(size_t)(r0 + 8) * 128 + c] =
                make_float2(oacc[mi][ni][2] * lacc[mi][1], oacc[mi][ni][3] * lacc[mi][1]);
        }
    }
}

// ---------------- fused: LN(out_proj + residual) -> pooling -> classifier (+deg cleanup) ----------------
__global__ __launch_bounds__(256) void k_lnpool_cls(const float* __restrict__ o2,
                          const float* __restrict__ hres,
                          const float* __restrict__ ga, const float* __restrict__ ba,
                          const float* __restrict__ W1, const float* __restrict__ b1,
                          const float* __restrict__ g1, const float* __restrict__ beta1,
                          const float* __restrict__ W2, const float* __restrict__ b2,
                          const float* __restrict__ W3, const float* __restrict__ b3,
                          float* __restrict__ out, int* __restrict__ deg) {
    if (blockIdx.x >= GG) {
        deg[(blockIdx.x - GG) * 256 + threadIdx.x] = 0;
        return;
    }
    __shared__ float ssum[8][128];
    __shared__ float smax[8][128];
    __shared__ float ps[384];
    __shared__ float z1[128];
    __shared__ float z2[64];
    __shared__ float red[8];
    const int g = blockIdx.x;
    const int w = threadIdx.x >> 5, lane = threadIdx.x & 31;
    {
        float4 gv = *(const float4*)&ga[lane * 4];
        float4 bv = *(const float4*)&ba[lane * 4];
        float4 psum = make_float4(0.f, 0.f, 0.f, 0.f);
        float4 pm = make_float4(-1e30f, -1e30f, -1e30f, -1e30f);
        #pragma unroll 2
        for (int i = 0; i < 32; i++) {
            size_t n = (size_t)g * NPG + w * 32 + i;
            float4 a = *(const float4*)(o2   + n * 128 + lane * 4);
            float4 b = *(const float4*)(hres + n * 128 + lane * 4);
            float x0 = a.x + b.x, x1 = a.y + b.y, x2 = a.z + b.z, x3 = a.w + b.w;
            float s  = x0 + x1 + x2 + x3;
            float s2 = x0*x0 + x1*x1 + x2*x2 + x3*x3;
            #pragma unroll
            for (int o = 16; o > 0; o >>= 1) {
                s  += __shfl_xor_sync(0xffffffffu, s,  o);
                s2 += __shfl_xor_sync(0xffffffffu, s2, o);
            }
            float m   = s  * (1.0f / 128.0f);
            float var = s2 * (1.0f / 128.0f) - m * m;
            float r   = rsqrtf(var + 1e-5f);
            float y0 = (x0 - m) * r * gv.x + bv.x;
            float y1 = (x1 - m) * r * gv.y + bv.y;
            float y2 = (x2 - m) * r * gv.z + bv.z;
            float y3 = (x3 - m) * r * gv.w + bv.w;
            psum.x += y0; psum.y += y1; psum.z += y2; psum.w += y3;
            pm.x = fmaxf(pm.x, y0); pm.y = fmaxf(pm.y, y1);
            pm.z = fmaxf(pm.z, y2); pm.w = fmaxf(pm.w, y3);
        }
        *(float4*)&ssum[w][lane * 4] = psum;
        *(float4*)&smax[w][lane * 4] = pm;
    }
    __syncthreads();
    {
        int f = threadIdx.x;
        if (f < 128) {
            float s = ssum[0][f], mx = smax[0][f];
            #pragma unroll
            for (int ww = 1; ww < 8; ww++) {
                s += ssum[ww][f];
                mx = fmaxf(mx, smax[ww][f]);
            }
            ps[f]       = s * (1.0f / 256.0f);
            ps[128 + f] = mx;
            ps[256 + f] = s;
        }
    }
    __syncthreads();
    const int f = threadIdx.x;
    float acc = 0.0f;
    if (f < 128) {
        acc = b1[f];
        for (int k = 0; k < 384; k++) acc = fmaf(ps[k], W1[k * 128 + f], acc);
    }
    {
        float s = (f < 128) ? acc : 0.0f;
        float s2 = s * s;
        #pragma unroll
        for (int o = 16; o > 0; o >>= 1) {
            s  += __shfl_xor_sync(0xffffffffu, s,  o);
            s2 += __shfl_xor_sync(0xffffffffu, s2, o);
        }
        if (w < 4 && lane == 0) { red[w] = s; red[4 + w] = s2; }
        __syncthreads();
        if (f < 128) {
            float ts  = red[0] + red[1] + red[2] + red[3];
            float ts2 = red[4] + red[5] + red[6] + red[7];
            float m   = ts  * (1.0f / 128.0f);
            float var = ts2 * (1.0f / 128.0f) - m * m;
            float r   = rsqrtf(var + 1e-5f);
            z1[f] = fmaxf((acc - m) * r * g1[f] + beta1[f], 0.0f);
        }
    }
    __syncthreads();
    if (f < 64) {
        float a = b2[f];
        #pragma unroll 8
        for (int k = 0; k < 128; k++) a = fmaf(z1[k], W2[k * 64 + f], a);
        z2[f] = fmaxf(a, 0.0f);
    }
    __syncthreads();
    if (f < 2) {
        float a = b3[f];
        #pragma unroll
        for (int k = 0; k < 64; k++) a = fmaf(z2[k], W3[k * 2 + f], a);
        out[g * 2 + f] = a;
    }
}

// ---------------- launch ----------------
extern "C" void kernel_launch(void* const* d_in, const int* in_sizes, int n_in,
                              void* d_out, int out_size) {
    const float* x     = (const float*)d_in[0];
    const int*   ei    = (const int*)  d_in[1];
    const float* W_in  = (const float*)d_in[3];
    const float* b_in  = (const float*)d_in[4];
    const float* g_in  = (const float*)d_in[5];
    const float* be_in = (const float*)d_in[6];
    const float* Wc    = (const float*)d_in[7];
    const float* bc    = (const float*)d_in[8];
    const float* gn    = (const float*)d_in[9];
    const float* bn    = (const float*)d_in[10];
    const float* Wq    = (const float*)d_in[11];
    const float* bq    = (const float*)d_in[12];
    const float* Wk    = (const float*)d_in[13];
    const float* bk    = (const float*)d_in[14];
    const float* Wv    = (const float*)d_in[15];
    const float* bv    = (const float*)d_in[16];
    const float* Wo    = (const float*)d_in[17];
    const float* bo    = (const float*)d_in[18];
    const float* ga    = (const float*)d_in[19];
    const float* ba    = (const float*)d_in[20];
    const float* W1    = (const float*)d_in[21];
    const float* b1    = (const float*)d_in[22];
    const float* g1    = (const float*)d_in[23];
    const float* beta1 = (const float*)d_in[24];
    const float* W2    = (const float*)d_in[25];
    const float* b2    = (const float*)d_in[26];
    const float* W3    = (const float*)d_in[27];
    const float* b3    = (const float*)d_in[28];
    float* out = (float*)d_out;

    const int* src = ei;
    const int* dst = ei + EE;

    float *p_h, *p_h2, *p_tmp, *p_q, *p_k, *p_v, *p_dis, *p_wct;
    ushort *p_hwbf;
    int *p_deg, *p_rp, *p_cur, *p_col, *p_done;
    cudaGetSymbolAddress((void**)&p_h,    g_h);
    cudaGetSymbolAddress((void**)&p_h2,   g_h2);
    cudaGetSymbolAddress((void**)&p_tmp,  g_tmp);
    cudaGetSymbolAddress((void**)&p_q,    g_q);
    cudaGetSymbolAddress((void**)&p_k,    g_k);
    cudaGetSymbolAddress((void**)&p_v,    g_v);
    cudaGetSymbolAddress((void**)&p_hwbf, g_hwbf);
    cudaGetSymbolAddress((void**)&p_wct,  g_wct);
    cudaGetSymbolAddress((void**)&p_deg,  g_deg);
    cudaGetSymbolAddress((void**)&p_rp,   g_rp);
    cudaGetSymbolAddress((void**)&p_cur,  g_cur);
    cudaGetSymbolAddress((void**)&p_col,  g_col);
    cudaGetSymbolAddress((void**)&p_dis,  g_dis);
    cudaGetSymbolAddress((void**)&p_done, g_done);

    const int HS = 4 * STG_W * sizeof(uint);   // 65536 B (2 stages x (A+B))
    cudaFuncSetAttribute(k_tgemm<0, 1>, cudaFuncAttributeMaxDynamicSharedMemorySize, HS);
    cudaFuncSetAttribute(k_tgemm<1, 0>, cudaFuncAttributeMaxDynamicSharedMemorySize, HS);
    cudaFuncSetAttribute(k_tgemm_qkv,   cudaFuncAttributeMaxDynamicSharedMemorySize, HS);
    cudaFuncSetAttribute(k_attn_tc,     cudaFuncAttributeMaxDynamicSharedMemorySize, AT_SMEM_B);

    // (1) hist+scan+wt  (2) fill+proj  (3) tgemm L1  (4) agg <- profiled
    k_histscan_wt<<<1024 + 48, 256>>>(dst, p_deg, p_rp, p_cur, p_dis, p_done, Wc, p_wct);
    k_fill_proj<<<1024 + 512, 256>>>(src, dst, p_cur, p_col,
                                     x, W_in, b_in, g_in, be_in, p_h);
    k_tgemm<0, 1><<<NN / 128, 256, HS>>>(p_h, p_wct, nullptr, p_dis, p_hwbf);
    k_gcn_agg<<<NN / 4, 128>>>(p_hwbf, p_h, p_rp, p_col, p_dis, bc, gn, bn, p_h2, 0);

    float* cur = p_h2;
    float* nxt = p_h;
    for (int i = 1; i < NLAYERS; i++) {
        k_tgemm<0, 1><<<NN / 128, 256, HS>>>(cur, p_wct + i * HID * HID, nullptr, p_dis, p_hwbf);
        k_gcn_agg<<<NN / 4, 128>>>(p_hwbf, cur, p_rp, p_col, p_dis,
                                   bc + i * HID, gn + i * HID, bn + i * HID, nxt, 1);
        float* t = cur; cur = nxt; nxt = t;
    }
    // cur == p_h2

    {
        dim3 grid(NN / 128, 3);
        k_tgemm_qkv<<<grid, 256, HS>>>(cur, Wq, bq, p_q, Wk, bk, p_k, Wv, bv, p_v);
    }
    k_attn_tc<<<GG * NH, 256, AT_SMEM_B>>>(p_q, p_k, p_v, p_tmp);
    k_tgemm<1, 0><<<NN / 128, 256, HS>>>(p_tmp, Wo, bo, nullptr, p_q);

    k_lnpool_cls<<<GG + 128, 256>>>(p_q, cur, ga, ba, W1, b1, g1, beta1,
                                    W2, b2, W3, b3, out, p_deg);
}

// round 16
// speedup vs baseline: 1.0428x; 1.0080x over previous
#include <cuda_runtime.h>
#include <math.h>

#define NN      32768      // nodes
#define GG      128        // graphs
#define NPG     256        // nodes per graph
#define HID     128
#define NH      8
#define DH      16
#define EE      1048576    // edges
#define NLAYERS 3

typedef unsigned long long ull;
typedef unsigned int uint;
typedef unsigned short ushort;

// ---------------- packed f32x2 helpers ----------------
__device__ __forceinline__ ull pk2(float lo, float hi) {
    ull r; asm("mov.b64 %0,{%1,%2};" : "=l"(r) : "f"(lo), "f"(hi)); return r;
}
__device__ __forceinline__ void up2(ull v, float& lo, float& hi) {
    asm("mov.b64 {%0,%1},%2;" : "=f"(lo), "=f"(hi) : "l"(v));
}
__device__ __forceinline__ ull add2(ull a, ull b) {
    ull d; asm("add.rn.f32x2 %0,%1,%2;" : "=l"(d) : "l"(a), "l"(b)); return d;
}
__device__ __forceinline__ uint bf2(float lo, float hi) {
    uint r; asm("cvt.rn.bf16x2.f32 %0,%1,%2;" : "=r"(r) : "f"(hi), "f"(lo)); return r;
}
// bf16x2 word -> packed f32x2 (ull): lo half -> low float, hi half -> high float
__device__ __forceinline__ ull bfp2(uint u) {
    return ((ull)(u & 0xffff0000u) << 32) | ((ull)(u << 16));
}
__device__ __forceinline__ uint tf32(float x) {
    uint r; asm("cvt.rna.tf32.f32 %0,%1;" : "=r"(r) : "f"(x)); return r;
}
__device__ __forceinline__ float tf32f(float x) { return __uint_as_float(tf32(x)); }
__device__ __forceinline__ void mma1688(float* c, uint a0, uint a1, uint a2, uint a3,
                                        uint b0, uint b1) {
    asm volatile("mma.sync.aligned.m16n8k8.row.col.f32.tf32.tf32.f32 "
        "{%0,%1,%2,%3},{%4,%5,%6,%7},{%8,%9},{%0,%1,%2,%3};"
        : "+f"(c[0]), "+f"(c[1]), "+f"(c[2]), "+f"(c[3])
        : "r"(a0), "r"(a1), "r"(a2), "r"(a3), "r"(b0), "r"(b1));
}
__device__ __forceinline__ void mmaf(float* c, float a0, float a1, float a2, float a3,
                                     float b0, float b1) {
    mma1688(c, __float_as_uint(a0), __float_as_uint(a1), __float_as_uint(a2),
            __float_as_uint(a3), __float_as_uint(b0), __float_as_uint(b1));
}
__device__ __forceinline__ void cpa16(uint dst, const void* src) {
    asm volatile("cp.async.ca.shared.global [%0], [%1], 16;" :: "r"(dst), "l"(src));
}
#define CP_COMMIT() asm volatile("cp.async.commit_group;" ::: "memory")
#define CP_WAIT(N)  asm volatile("cp.async.wait_group %0;" :: "n"(N) : "memory")

// ---------------- scratch (device globals; zero-initialized at module load) ----------------
__device__ float  g_h   [NN * HID];
__device__ float  g_h2  [NN * HID];
__device__ float  g_tmp [NN * HID];
__device__ float  g_q   [NN * HID];
__device__ float  g_k   [NN * HID];
__device__ float  g_v   [NN * HID];
__device__ ushort g_hwbf[NN * HID];
__device__ float  g_wct [NLAYERS * HID * HID];
__device__ int    g_deg[NN];        // zero at invocation start (cleanup re-zeros)
__device__ int    g_rp [NN + 1];
__device__ int    g_cur[NN];
__device__ int    g_col[EE];        // stores BYTE offsets (src_node * 256)
__device__ float  g_dis[NN];
__device__ int    g_done[1];

// ---------------- kernel 1: hist + scan (last-block) + weight transpose ----------------
__global__ __launch_bounds__(256) void k_histscan_wt(const int* __restrict__ dst,
                        int* __restrict__ deg, int* __restrict__ rp,
                        int* __restrict__ cur, float* __restrict__ dis,
                        int* __restrict__ done,
                        const float* __restrict__ Wc, float* __restrict__ WT) {
    if (blockIdx.x >= 1024) {
        int w = (blockIdx.x - 1024) * 8 + (threadIdx.x >> 5);   // 0..383
        int l = w >> 7, f = w & 127;
        int lane = threadIdx.x & 31;
        const float* Wl = Wc + l * 16384;
        float4 v;
        v.x = __ldg(&Wl[(lane * 4 + 0) * 128 + f]);
        v.y = __ldg(&Wl[(lane * 4 + 1) * 128 + f]);
        v.z = __ldg(&Wl[(lane * 4 + 2) * 128 + f]);
        v.w = __ldg(&Wl[(lane * 4 + 3) * 128 + f]);
        *(float4*)&WT[(size_t)l * 16384 + f * 128 + lane * 4] = v;
        return;
    }
    int e = (blockIdx.x * 256 + threadIdx.x) * 4;
    int4 d = *(const int4*)&dst[e];
    atomicAdd(&deg[d.x], 1);
    atomicAdd(&deg[d.y], 1);
    atomicAdd(&deg[d.z], 1);
    atomicAdd(&deg[d.w], 1);
    __threadfence();
    __shared__ int amLast;
    if (threadIdx.x == 0)
        amLast = (atomicAdd(done, 1) == 1023);
    __syncthreads();
    if (!amLast) return;

    __shared__ int part[256];
    const int tid = threadIdx.x;
    const int base = tid * 128;
    int s = 0;
    for (int i = 0; i < 128; i++) s += deg[base + i];
    part[tid] = s;
    __syncthreads();
    for (int off = 1; off < 256; off <<= 1) {
        int t = (tid >= off) ? part[tid - off] : 0;
        __syncthreads();
        part[tid] += t;
        __syncthreads();
    }
    int run = part[tid] - s;
    for (int i = 0; i < 128; i++) {
        int d0 = deg[base + i];
        rp[base + i]  = run;
        cur[base + i] = run;
        dis[base + i] = rsqrtf((float)d0 + 1.0f);
        run += d0;
    }
    if (tid == 255) rp[NN] = run;
    if (tid == 0) *done = 0;
}

// ---------------- kernel 2: CSR fill (byte offsets) + input projection ----------------
__global__ __launch_bounds__(256) void k_fill_proj(const int* __restrict__ src,
                       const int* __restrict__ dst,
                       int* __restrict__ cur, int* __restrict__ col,
                       const float* __restrict__ x, const float* __restrict__ W,
                       const float* __restrict__ b, const float* __restrict__ g,
                       const float* __restrict__ be, float* __restrict__ out) {
    if (blockIdx.x < 1024) {
        int e = (blockIdx.x * 256 + threadIdx.x) * 4;
        int4 s = *(const int4*)&src[e];
        int4 d = *(const int4*)&dst[e];
        int p0 = atomicAdd(&cur[d.x], 1);
        int p1 = atomicAdd(&cur[d.y], 1);
        int p2 = atomicAdd(&cur[d.z], 1);
        int p3 = atomicAdd(&cur[d.w], 1);
        // store BYTE offset of the bf16 row: node * 128 * 2
        col[p0] = s.x << 8; col[p1] = s.y << 8;
        col[p2] = s.z << 8; col[p3] = s.w << 8;
        return;
    }
    const int lane = threadIdx.x & 31;
    const int n0 = ((blockIdx.x - 1024) * 8 + (threadIdx.x >> 5)) * 8;
    float4 w[15];
    #pragma unroll
    for (int k = 0; k < 15; k++) w[k] = *(const float4*)&W[k * 128 + lane * 4];
    const float4 bb = *(const float4*)&b[lane * 4];
    const float4 gv = *(const float4*)&g[lane * 4];
    const float4 bv = *(const float4*)&be[lane * 4];
    float4 xv = make_float4(0.f, 0.f, 0.f, 0.f);
    if (lane < 30) xv = *(const float4*)&x[n0 * 15 + lane * 4];

    #pragma unroll
    for (int i = 0; i < 8; i++) {
        float4 acc = bb;
        #pragma unroll
        for (int k = 0; k < 15; k++) {
            const int e = i * 15 + k;
            const int srcLane = e >> 2, comp = e & 3;
            float xe = (comp == 0) ? xv.x : (comp == 1) ? xv.y : (comp == 2) ? xv.z : xv.w;
            float xk = __shfl_sync(0xffffffffu, xe, srcLane);
            acc.x = fmaf(xk, w[k].x, acc.x); acc.y = fmaf(xk, w[k].y, acc.y);
            acc.z = fmaf(xk, w[k].z, acc.z); acc.w = fmaf(xk, w[k].w, acc.w);
        }
        float s  = acc.x + acc.y + acc.z + acc.w;
        float s2 = acc.x*acc.x + acc.y*acc.y + acc.z*acc.z + acc.w*acc.w;
        #pragma unroll
        for (int o = 16; o > 0; o >>= 1) {
            s  += __shfl_xor_sync(0xffffffffu, s,  o);
            s2 += __shfl_xor_sync(0xffffffffu, s2, o);
        }
        float m   = s * (1.0f / 128.0f);
        float var = s2 * (1.0f / 128.0f) - m * m;
        float r   = rsqrtf(var + 1e-5f);
        float4 y;
        y.x = fmaxf((acc.x - m) * r * gv.x + bv.x, 0.0f);
        y.y = fmaxf((acc.y - m) * r * gv.y + bv.y, 0.0f);
        y.z = fmaxf((acc.z - m) * r * gv.z + bv.z, 0.0f);
        y.w = fmaxf((acc.w - m) * r * gv.w + bv.w, 0.0f);
        *(float4*)(out + (size_t)(n0 + i) * 128 + lane * 4) = y;
    }
}

// ---------------- tf32 tensor-core GEMM (2-stage cp.async; R13 config) ----------------
#define STG_W 4096

__device__ __forceinline__ void stage_issue(uint smA, uint smB,
                                            const float* __restrict__ A,
                                            const float* __restrict__ B,
                                            int row0, int kt, int t) {
    #pragma unroll
    for (int i = 0; i < 4; i++) {
        int idx = i * 256 + t;
        int r = idx >> 3, c4 = (idx & 7) * 4;
        int cs = c4 ^ ((r & 7) << 2);
        cpa16(smA + (uint)(r * 32 + cs) * 4u, &A[(size_t)(row0 + r) * 128 + kt * 32 + c4]);
    }
    #pragma unroll
    for (int i = 0; i < 4; i++) {
        int idx = i * 256 + t;
        int r = idx >> 3, c4 = (idx & 7) * 4;
        int cs = c4 ^ ((r & 7) << 2);
        cpa16(smB + (uint)(r * 32 + cs) * 4u, &B[(size_t)r * 128 + kt * 32 + c4]);
    }
}

template <int BIAS, int BF16OUT>
__device__ __forceinline__ void tgemm_dev(uint* sm, const float* __restrict__ A,
                                          const float* __restrict__ B,
                                          const float* __restrict__ bias,
                                          const float* __restrict__ dis,
                                          void* __restrict__ Cv) {
    const int t = threadIdx.x;
    const int lane = t & 31, warp = t >> 5;
    const int row0 = blockIdx.x * 128;
    const int m0 = (warp >> 2) * 64;
    const int n0 = (warp & 3) * 32;
    const int gid = lane >> 2, tg = lane & 3;
    const uint smbase = (uint)__cvta_generic_to_shared(sm);

    stage_issue(smbase, smbase + STG_W * 4u, A, B, row0, 0, t);
    CP_COMMIT();
    stage_issue(smbase + 2u * STG_W * 4u, smbase + 3u * STG_W * 4u, A, B, row0, 1, t);
    CP_COMMIT();

    float acc[4][4][4];
    #pragma unroll
    for (int mi = 0; mi < 4; mi++)
        #pragma unroll
        for (int ni = 0; ni < 4; ni++)
            #pragma unroll
            for (int q = 0; q < 4; q++) acc[mi][ni][q] = 0.0f;

    #pragma unroll
    for (int kt = 0; kt < 4; kt++) {
        if (kt < 3) { CP_WAIT(1); } else { CP_WAIT(0); }
        __syncthreads();
        const uint* As = sm + (kt & 1) * 2 * STG_W;
        const uint* Bs = As + STG_W;
        #pragma unroll
        for (int ks = 0; ks < 4; ks++) {
            const int c0 = (ks * 8 + tg) ^ (gid << 2);
            const int c1 = c0 ^ 4;
            uint af[4][4];
            #pragma unroll
            for (int mi = 0; mi < 4; mi++) {
                const uint* a0 = &As[(m0 + mi * 16 + gid) * 32];
                const uint* a1 = &As[(m0 + mi * 16 + gid + 8) * 32];
                af[mi][0] = a0[c0]; af[mi][1] = a1[c0];
                af[mi][2] = a0[c1]; af[mi][3] = a1[c1];
            }
            uint bf[4][2];
            #pragma unroll
            for (int ni = 0; ni < 4; ni++) {
                const uint* b0 = &Bs[(n0 + ni * 8 + gid) * 32];
                bf[ni][0] = b0[c0]; bf[ni][1] = b0[c1];
            }
            #pragma unroll
            for (int mi = 0; mi < 4; mi++)
                #pragma unroll
                for (int ni = 0; ni < 4; ni++)
                    mma1688(acc[mi][ni], af[mi][0], af[mi][1], af[mi][2], af[mi][3],
                            bf[ni][0], bf[ni][1]);
        }
        __syncthreads();
        if (kt < 2) {
            int s = kt + 2;
            uint ab = smbase + (uint)(s & 1) * 2u * STG_W * 4u;
            stage_issue(ab, ab + STG_W * 4u, A, B, row0, s, t);
            CP_COMMIT();
        }
    }

    float2 bb[4];
    #pragma unroll
    for (int ni = 0; ni < 4; ni++) {
        if (BIAS) bb[ni] = *(const float2*)&bias[n0 + ni * 8 + tg * 2];
        else      bb[ni] = make_float2(0.f, 0.f);
    }
    #pragma unroll
    for (int mi = 0; mi < 4; mi++) {
        int r = row0 + m0 + mi * 16 + gid;
        float d0 = 1.0f, d1 = 1.0f;
        if (BF16OUT) { d0 = __ldg(&dis[r]); d1 = __ldg(&dis[r + 8]); }
        #pragma unroll
        for (int ni = 0; ni < 4; ni++) {
            int c = n0 + ni * 8 + tg * 2;
            float v0 = acc[mi][ni][0] + bb[ni].x;
            float v1 = acc[mi][ni][1] + bb[ni].y;
            float v2 = acc[mi][ni][2] + bb[ni].x;
            float v3 = acc[mi][ni][3] + bb[ni].y;
            if (BF16OUT) {
                ushort* Cb = (ushort*)Cv;
                *(uint*)(Cb + (size_t)r * 128 + c)       = bf2(v0 * d0, v1 * d0);
                *(uint*)(Cb + (size_t)(r + 8) * 128 + c) = bf2(v2 * d1, v3 * d1);
            } else {
                float* C = (float*)Cv;
                *(float2*)&C[(size_t)r * 128 + c]       = make_float2(v0, v1);
                *(float2*)&C[(size_t)(r + 8) * 128 + c] = make_float2(v2, v3);
            }
        }
    }
}

template <int BIAS, int BF16OUT>
__global__ __launch_bounds__(256, 2) void k_tgemm(const float* __restrict__ A,
                                                  const float* __restrict__ B,
                                                  const float* __restrict__ bias,
                                                  const float* __restrict__ dis,
                                                  void* __restrict__ C) {
    extern __shared__ uint smx[];
    tgemm_dev<BIAS, BF16OUT>(smx, A, B, bias, dis, C);
}

__global__ __launch_bounds__(256, 2) void k_tgemm_qkv(const float* __restrict__ A,
    const float* __restrict__ Wq, const float* __restrict__ bq, float* __restrict__ q,
    const float* __restrict__ Wk, const float* __restrict__ bk, float* __restrict__ k,
    const float* __restrict__ Wv, const float* __restrict__ bv, float* __restrict__ v) {
    extern __shared__ uint smx[];
    int s = blockIdx.y;
    const float* B  = (s == 0) ? Wq : (s == 1) ? Wk : Wv;
    const float* bi = (s == 0) ? bq : (s == 1) ? bk : bv;
    float*       C  = (s == 0) ? q  : (s == 1) ? k  : v;
    tgemm_dev<1, 0>(smx, A, B, bi, nullptr, C);
}

// ---------------- GCN aggregate (pre-scaled bf16 rows; byte-offset col) ----------------
__global__ __launch_bounds__(128) void k_gcn_agg(const ushort* __restrict__ hw,
                          const float* __restrict__ hin,
                          const int* __restrict__ rp, const int* __restrict__ col,
                          const float* __restrict__ dis,
                          const float* __restrict__ bc, const float* __restrict__ gn,
                          const float* __restrict__ bn, float* __restrict__ hout,
                          int residual) {
    const int lane = threadIdx.x & 31;
    const int n = blockIdx.x * 4 + (threadIdx.x >> 5);
    const float dn = dis[n];
    const char* hwb = (const char*)hw + lane * 8;   // lane-local base

    uint2 u = *(const uint2*)(hwb + ((size_t)n << 8));
    ull a0 = bfp2(u.x), a1 = bfp2(u.y);   // self row (already dis[n]-scaled)

    int e = rp[n], end = rp[n + 1];
    for (; e + 8 <= end; e += 8) {
        int   off[8];
        uint2 ui[8];
        #pragma unroll
        for (int q = 0; q < 8; q++) off[q] = __ldg(&col[e + q]);
        #pragma unroll
        for (int q = 0; q < 8; q++) ui[q] = *(const uint2*)(hwb + off[q]);
        #pragma unroll
        for (int q = 0; q < 8; q++) {
            a0 = add2(a0, bfp2(ui[q].x));
            a1 = add2(a1, bfp2(ui[q].y));
        }
    }
    for (; e < end; e++) {
        int off = __ldg(&col[e]);
        uint2 u0 = *(const uint2*)(hwb + off);
        a0 = add2(a0, bfp2(u0.x));
        a1 = add2(a1, bfp2(u0.y));
    }

    float x0, x1, x2, x3;
    up2(a0, x0, x1); up2(a1, x2, x3);
    float4 bcv = *(const float4*)&bc[lane * 4];
    x0 = fmaf(dn, x0, bcv.x); x1 = fmaf(dn, x1, bcv.y);
    x2 = fmaf(dn, x2, bcv.z); x3 = fmaf(dn, x3, bcv.w);

    float s  = x0 + x1 + x2 + x3;
    float s2 = x0 * x0 + x1 * x1 + x2 * x2 + x3 * x3;
    #pragma unroll
    for (int o = 16; o > 0; o >>= 1) {
        s  += __shfl_xor_sync(0xffffffffu, s,  o);
        s2 += __shfl_xor_sync(0xffffffffu, s2, o);
    }
    float m   = s  * (1.0f / 128.0f);
    float var = s2 * (1.0f / 128.0f) - m * m;
    float r   = rsqrtf(var + 1e-5f);

    float4 gv = *(const float4*)&gn[lane * 4];
    float4 bv = *(const float4*)&bn[lane * 4];
    float y0 = fmaxf((x0 - m) * r * gv.x + bv.x, 0.0f);
    float y1 = fmaxf((x1 - m) * r * gv.y + bv.y, 0.0f);
    float y2 = fmaxf((x2 - m) * r * gv.z + bv.z, 0.0f);
    float y3 = fmaxf((x3 - m) * r * gv.w + bv.w, 0.0f);
    if (residual) {
        float4 hr = *(const float4*)(hin + (size_t)n * 128 + lane * 4);
        y0 += hr.x; y1 += hr.y; y2 += hr.z; y3 += hr.w;
    }
    *(float4*)(hout + (size_t)n * 128 + lane * 4) = make_float4(y0, y1, y2, y3);
}

// ---------------- tensor-core flash attention (exp-phase diet) ----------------
// fminf dropped: |s| <= PRE*||q16||*||k16|| <= 0.36*128 = 46 << exp2 overflow (127).
// trunc13 dropped: mma's internal RZ truncation of P biases softmax by <= 2^-14 avg.
#define AT_KS 20
#define AT_VS 260
#define AT_PS 36
#define AT_KS_OFF 0
#define AT_VT_OFF (256 * AT_KS)
#define AT_PW_OFF (AT_VT_OFF + 16 * AT_VS)
#define AT_SMEM_W (AT_PW_OFF + 8 * 32 * AT_PS)
#define AT_SMEM_B (AT_SMEM_W * 4)

__global__ __launch_bounds__(256, 2) void k_attn_tc(const float* __restrict__ qg,
                                                    const float* __restrict__ kg,
                                                    const float* __restrict__ vg,
                                                    float* __restrict__ og) {
    extern __shared__ float smf[];
    float* Ks = smf + AT_KS_OFF;
    float* Vt = smf + AT_VT_OFF;
    const int t = threadIdx.x;
    const int lane = t & 31, warp = t >> 5;
    const int gid = lane >> 2, tg = lane & 3;
    float* Pw = smf + AT_PW_OFF + warp * (32 * AT_PS);
    const int g = blockIdx.x >> 3, h = blockIdx.x & 7;
    const size_t base = (size_t)(g * NPG) * 128 + h * 16;
    const float PRE = 0.25f * 1.4426950408889634f;

    {
        const float4* kp = (const float4*)(kg + base + (size_t)t * 128);
        float* kr = Ks + t * AT_KS;
        #pragma unroll
        for (int i = 0; i < 4; i++) {
            float4 v = kp[i];
            kr[i*4+0] = tf32f(v.x); kr[i*4+1] = tf32f(v.y);
            kr[i*4+2] = tf32f(v.z); kr[i*4+3] = tf32f(v.w);
        }
        const float4* vp = (const float4*)(vg + base + (size_t)t * 128);
        #pragma unroll
        for (int i = 0; i < 4; i++) {
            float4 v = vp[i];
            Vt[(i*4+0) * AT_VS + t] = tf32f(v.x);
            Vt[(i*4+1) * AT_VS + t] = tf32f(v.y);
            Vt[(i*4+2) * AT_VS + t] = tf32f(v.z);
            Vt[(i*4+3) * AT_VS + t] = tf32f(v.w);
        }
    }
    const int wm0 = warp * 32;
    float qf[2][8];
    #pragma unroll
    for (int mi = 0; mi < 2; mi++) {
        size_t r0 = (size_t)(g * NPG + wm0 + mi * 16 + gid) * 128 + h * 16;
        size_t r1 = r0 + 8 * 128;
        #pragma unroll
        for (int ks = 0; ks < 2; ks++) {
            qf[mi][ks*4+0] = tf32f(qg[r0 + ks*8 + tg]     * PRE);
            qf[mi][ks*4+1] = tf32f(qg[r1 + ks*8 + tg]     * PRE);
            qf[mi][ks*4+2] = tf32f(qg[r0 + ks*8 + tg + 4] * PRE);
            qf[mi][ks*4+3] = tf32f(qg[r1 + ks*8 + tg + 4] * PRE);
        }
    }
    __syncthreads();

    float oacc[2][2][4];
    float lacc[2][2];
    #pragma unroll
    for (int mi = 0; mi < 2; mi++) {
        lacc[mi][0] = 0.0f; lacc[mi][1] = 0.0f;
        #pragma unroll
        for (int ni = 0; ni < 2; ni++)
            #pragma unroll
            for (int q = 0; q < 4; q++) oacc[mi][ni][q] = 0.0f;
    }

    #pragma unroll 1
    for (int jt = 0; jt < 8; jt++) {
        const int j0 = jt * 32;
        float sacc[2][4][4];
        #pragma unroll
        for (int mi = 0; mi < 2; mi++)
            #pragma unroll
            for (int ni = 0; ni < 4; ni++)
                #pragma unroll
                for (int q = 0; q < 4; q++) sacc[mi][ni][q] = 0.0f;
        #pragma unroll
        for (int ks = 0; ks < 2; ks++) {
            float bf[4][2];
            #pragma unroll
            for (int ni = 0; ni < 4; ni++) {
                const float* kb = &Ks[(j0 + ni * 8 + gid) * AT_KS + ks * 8 + tg];
                bf[ni][0] = kb[0]; bf[ni][1] = kb[4];
            }
            #pragma unroll
            for (int mi = 0; mi < 2; mi++)
                #pragma unroll
                for (int ni = 0; ni < 4; ni++)
                    mmaf(sacc[mi][ni], qf[mi][ks*4+0], qf[mi][ks*4+1],
                         qf[mi][ks*4+2], qf[mi][ks*4+3], bf[ni][0], bf[ni][1]);
        }
        __syncwarp();
        #pragma unroll
        for (int mi = 0; mi < 2; mi++) {
            #pragma unroll
            for (int ni = 0; ni < 4; ni++) {
                float p0 = exp2f(sacc[mi][ni][0]);
                float p1 = exp2f(sacc[mi][ni][1]);
                float p2 = exp2f(sacc[mi][ni][2]);
                float p3 = exp2f(sacc[mi][ni][3]);
                lacc[mi][0] += p0 + p1;
                lacc[mi][1] += p2 + p3;
                int c = ni * 8 + tg * 2;
                *(float2*)&Pw[(mi * 16 + gid) * AT_PS + c]     = make_float2(p0, p1);
                *(float2*)&Pw[(mi * 16 + gid + 8) * AT_PS + c] = make_float2(p2, p3);
            }
        }
        __syncwarp();
        #pragma unroll
        for (int ks = 0; ks < 4; ks++) {
            float vb[2][2];
            #pragma unroll
            for (int ni = 0; ni < 2; ni++) {
                const float* vr = &Vt[(ni * 8 + gid) * AT_VS + j0 + ks * 8 + tg];
                vb[ni][0] = vr[0]; vb[ni][1] = vr[4];
            }
            float af[2][4];
            #pragma unroll
            for (int mi = 0; mi < 2; mi++) {
                const float* p0 = &Pw[(mi * 16 + gid) * AT_PS + ks * 8 + tg];
                const float* p1 = &Pw[(mi * 16 + gid + 8) * AT_PS + ks * 8 + tg];
                af[mi][0] = p0[0]; af[mi][1] = p1[0];
                af[mi][2] = p0[4]; af[mi][3] = p1[4];
            }
            #pragma unroll
            for (int mi = 0; mi < 2; mi++)
                #pragma unroll
                for (int ni = 0; ni < 2; ni++)
                    mmaf(oacc[mi][ni], af[mi][0], af[mi][1], af[mi][2], af[mi][3],
                         vb[ni][0], vb[ni][1]);
        }
        __syncwarp();
    }

    #pragma unroll
    for (int mi = 0; mi < 2; mi++) {
        #pragma unroll
        for (int u = 0; u < 2; u++) {
            float l = lacc[mi][u];
            l += __shfl_xor_sync(0xffffffffu, l, 1);
            l += __shfl_xor_sync(0xffffffffu, l, 2);
            lacc[mi][u] = 1.0f / l;
        }
    }
    #pragma unroll
    for (int mi = 0; mi < 2; mi++) {
        int r0 = g * NPG + wm0 + mi * 16 + gid;
        #pragma unroll
        for (int ni = 0; ni < 2; ni++) {
            int c = h * 16 + ni * 8 + tg * 2;
            *(float2*)&og[(size_t)r0 * 128 + c] =
                make_float2(oacc[mi][ni][0] * lacc[mi][0], oacc[mi][ni][1] * lacc[mi][0]);
            *(float2*)&og[(size_t)(r0 + 8) * 128 + c] =
                make_float2(oacc[mi][ni][2] * lacc[mi][1], oacc[mi][ni][3] * lacc[mi][1]);
        }
    }
}

// ---------------- fused: LN(out_proj + residual) -> pooling -> classifier (+deg cleanup) ----------------
__global__ __launch_bounds__(256) void k_lnpool_cls(const float* __restrict__ o2,
                          const float* __restrict__ hres,
                          const float* __restrict__ ga, const float* __restrict__ ba,
                          const float* __restrict__ W1, const float* __restrict__ b1,
                          const float* __restrict__ g1, const float* __restrict__ beta1,
                          const float* __restrict__ W2, const float* __restrict__ b2,
                          const float* __restrict__ W3, const float* __restrict__ b3,
                          float* __restrict__ out, int* __restrict__ deg) {
    if (blockIdx.x >= GG) {
        deg[(blockIdx.x - GG) * 256 + threadIdx.x] = 0;
        return;
    }
    __shared__ float ssum[8][128];
    __shared__ float smax[8][128];
    __shared__ float ps[384];
    __shared__ float z1[128];
    __shared__ float z2[64];
    __shared__ float red[8];
    const int g = blockIdx.x;
    const int w = threadIdx.x >> 5, lane = threadIdx.x & 31;
    {
        float4 gv = *(const float4*)&ga[lane * 4];
        float4 bv = *(const float4*)&ba[lane * 4];
        float4 psum = make_float4(0.f, 0.f, 0.f, 0.f);
        float4 pm = make_float4(-1e30f, -1e30f, -1e30f, -1e30f);
        #pragma unroll 2
        for (int i = 0; i < 32; i++) {
            size_t n = (size_t)g * NPG + w * 32 + i;
            float4 a = *(const float4*)(o2   + n * 128 + lane * 4);
            float4 b = *(const float4*)(hres + n * 128 + lane * 4);
            float x0 = a.x + b.x, x1 = a.y + b.y, x2 = a.z + b.z, x3 = a.w + b.w;
            float s  = x0 + x1 + x2 + x3;
            float s2 = x0*x0 + x1*x1 + x2*x2 + x3*x3;
            #pragma unroll
            for (int o = 16; o > 0; o >>= 1) {
                s  += __shfl_xor_sync(0xffffffffu, s,  o);
                s2 += __shfl_xor_sync(0xffffffffu, s2, o);
            }
            float m   = s  * (1.0f / 128.0f);
            float var = s2 * (1.0f / 128.0f) - m * m;
            float r   = rsqrtf(var + 1e-5f);
            float y0 = (x0 - m) * r * gv.x + bv.x;
            float y1 = (x1 - m) * r * gv.y + bv.y;
            float y2 = (x2 - m) * r * gv.z + bv.z;
            float y3 = (x3 - m) * r * gv.w + bv.w;
            psum.x += y0; psum.y += y1; psum.z += y2; psum.w += y3;
            pm.x = fmaxf(pm.x, y0); pm.y = fmaxf(pm.y, y1);
            pm.z = fmaxf(pm.z, y2); pm.w = fmaxf(pm.w, y3);
        }
        *(float4*)&ssum[w][lane * 4] = psum;
        *(float4*)&smax[w][lane * 4] = pm;
    }
    __syncthreads();
    {
        int f = threadIdx.x;
        if (f < 128) {
            float s = ssum[0][f], mx = smax[0][f];
            #pragma unroll
            for (int ww = 1; ww < 8; ww++) {
                s += ssum[ww][f];
                mx = fmaxf(mx, smax[ww][f]);
            }
            ps[f]       = s * (1.0f / 256.0f);
            ps[128 + f] = mx;
            ps[256 + f] = s;
        }
    }
    __syncthreads();
    const int f = threadIdx.x;
    float acc = 0.0f;
    if (f < 128) {
        acc = b1[f];
        for (int k = 0; k < 384; k++) acc = fmaf(ps[k], W1[k * 128 + f], acc);
    }
    {
        float s = (f < 128) ? acc : 0.0f;
        float s2 = s * s;
        #pragma unroll
        for (int o = 16; o > 0; o >>= 1) {
            s  += __shfl_xor_sync(0xffffffffu, s,  o);
            s2 += __shfl_xor_sync(0xffffffffu, s2, o);
        }
        if (w < 4 && lane == 0) { red[w] = s; red[4 + w] = s2; }
        __syncthreads();
        if (f < 128) {
            float ts  = red[0] + red[1] + red[2] + red[3];
            float ts2 = red[4] + red[5] + red[6] + red[7];
            float m   = ts  * (1.0f / 128.0f);
            float var = ts2 * (1.0f / 128.0f) - m * m;
            float r   = rsqrtf(var + 1e-5f);
            z1[f] = fmaxf((acc - m) * r * g1[f] + beta1[f], 0.0f);
        }
    }
    __syncthreads();
    if (f < 64) {
        float a = b2[f];
        #pragma unroll 8
        for (int k = 0; k < 128; k++) a = fmaf(z1[k], W2[k * 64 + f], a);
        z2[f] = fmaxf(a, 0.0f);
    }
    __syncthreads();
    if (f < 2) {
        float a = b3[f];
        #pragma unroll
        for (int k = 0; k < 64; k++) a = fmaf(z2[k], W3[k * 2 + f], a);
        out[g * 2 + f] = a;
    }
}

// ---------------- launch ----------------
extern "C" void kernel_launch(void* const* d_in, const int* in_sizes, int n_in,
                              void* d_out, int out_size) {
    const float* x     = (const float*)d_in[0];
    const int*   ei    = (const int*)  d_in[1];
    const float* W_in  = (const float*)d_in[3];
    const float* b_in  = (const float*)d_in[4];
    const float* g_in  = (const float*)d_in[5];
    const float* be_in = (const float*)d_in[6];
    const float* Wc    = (const float*)d_in[7];
    const float* bc    = (const float*)d_in[8];
    const float* gn    = (const float*)d_in[9];
    const float* bn    = (const float*)d_in[10];
    const float* Wq    = (const float*)d_in[11];
    const float* bq    = (const float*)d_in[12];
    const float* Wk    = (const float*)d_in[13];
    const float* bk    = (const float*)d_in[14];
    const float* Wv    = (const float*)d_in[15];
    const float* bv    = (const float*)d_in[16];
    const float* Wo    = (const float*)d_in[17];
    const float* bo    = (const float*)d_in[18];
    const float* ga    = (const float*)d_in[19];
    const float* ba    = (const float*)d_in[20];
    const float* W1    = (const float*)d_in[21];
    const float* b1    = (const float*)d_in[22];
    const float* g1    = (const float*)d_in[23];
    const float* beta1 = (const float*)d_in[24];
    const float* W2    = (const float*)d_in[25];
    const float* b2    = (const float*)d_in[26];
    const float* W3    = (const float*)d_in[27];
    const float* b3    = (const float*)d_in[28];
    float* out = (float*)d_out;

    const int* src = ei;
    const int* dst = ei + EE;

    float *p_h, *p_h2, *p_tmp, *p_q, *p_k, *p_v, *p_dis, *p_wct;
    ushort *p_hwbf;
    int *p_deg, *p_rp, *p_cur, *p_col, *p_done;
    cudaGetSymbolAddress((void**)&p_h,    g_h);
    cudaGetSymbolAddress((void**)&p_h2,   g_h2);
    cudaGetSymbolAddress((void**)&p_tmp,  g_tmp);
    cudaGetSymbolAddress((void**)&p_q,    g_q);
    cudaGetSymbolAddress((void**)&p_k,    g_k);
    cudaGetSymbolAddress((void**)&p_v,    g_v);
    cudaGetSymbolAddress((void**)&p_hwbf, g_hwbf);
    cudaGetSymbolAddress((void**)&p_wct,  g_wct);
    cudaGetSymbolAddress((void**)&p_deg,  g_deg);
    cudaGetSymbolAddress((void**)&p_rp,   g_rp);
    cudaGetSymbolAddress((void**)&p_cur,  g_cur);
    cudaGetSymbolAddress((void**)&p_col,  g_col);
    cudaGetSymbolAddress((void**)&p_dis,  g_dis);
    cudaGetSymbolAddress((void**)&p_done, g_done);

    const int HS = 4 * STG_W * sizeof(uint);   // 65536 B (2 stages x (A+B))
    cudaFuncSetAttribute(k_tgemm<0, 1>, cudaFuncAttributeMaxDynamicSharedMemorySize, HS);
    cudaFuncSetAttribute(k_tgemm<1, 0>, cudaFuncAttributeMaxDynamicSharedMemorySize, HS);
    cudaFuncSetAttribute(k_tgemm_qkv,   cudaFuncAttributeMaxDynamicSharedMemorySize, HS);
    cudaFuncSetAttribute(k_attn_tc,     cudaFuncAttributeMaxDynamicSharedMemorySize, AT_SMEM_B);

    // (1) hist+scan+wt  (2) fill+proj  (3) tgemm L1  (4) agg <- profiled
    k_histscan_wt<<<1024 + 48, 256>>>(dst, p_deg, p_rp, p_cur, p_dis, p_done, Wc, p_wct);
    k_fill_proj<<<1024 + 512, 256>>>(src, dst, p_cur, p_col,
                                     x, W_in, b_in, g_in, be_in, p_h);
    k_tgemm<0, 1><<<NN / 128, 256, HS>>>(p_h, p_wct, nullptr, p_dis, p_hwbf);
    k_gcn_agg<<<NN / 4, 128>>>(p_hwbf, p_h, p_rp, p_col, p_dis, bc, gn, bn, p_h2, 0);

    float* cur = p_h2;
    float* nxt = p_h;
    for (int i = 1; i < NLAYERS; i++) {
        k_tgemm<0, 1><<<NN / 128, 256, HS>>>(cur, p_wct + i * HID * HID, nullptr, p_dis, p_hwbf);
        k_gcn_agg<<<NN / 4, 128>>>(p_hwbf, cur, p_rp, p_col, p_dis,
                                   bc + i * HID, gn + i * HID, bn + i * HID, nxt, 1);
        float* t = cur; cur = nxt; nxt = t;
    }
    // cur == p_h2

    {
        dim3 grid(NN / 128, 3);
        k_tgemm_qkv<<<grid, 256, HS>>>(cur, Wq, bq, p_q, Wk, bk, p_k, Wv, bv, p_v);
    }
    k_attn_tc<<<GG * NH, 256, AT_SMEM_B>>>(p_q, p_k, p_v, p_tmp);
    k_tgemm<1, 0><<<NN / 128, 256, HS>>>(p_tmp, Wo, bo, nullptr, p_q);

    k_lnpool_cls<<<GG + 128, 256>>>(p_q, cur, ga, ba, W1, b1, g1, beta1,
                                    W2, b2, W3, b3, out, p_deg);
}

// round 17
// speedup vs baseline: 1.0726x; 1.0286x over previous
#include <cuda_runtime.h>
#include <math.h>

#define NN      32768      // nodes
#define GG      128        // graphs
#define NPG     256        // nodes per graph
#define HID     128
#define NH      8
#define DH      16
#define EE      1048576    // edges
#define NLAYERS 3

typedef unsigned long long ull;
typedef unsigned int uint;
typedef unsigned short ushort;

// ---------------- packed f32x2 helpers ----------------
__device__ __forceinline__ ull pk2(float lo, float hi) {
    ull r; asm("mov.b64 %0,{%1,%2};" : "=l"(r) : "f"(lo), "f"(hi)); return r;
}
__device__ __forceinline__ void up2(ull v, float& lo, float& hi) {
    asm("mov.b64 {%0,%1},%2;" : "=f"(lo), "=f"(hi) : "l"(v));
}
__device__ __forceinline__ ull add2(ull a, ull b) {
    ull d; asm("add.rn.f32x2 %0,%1,%2;" : "=l"(d) : "l"(a), "l"(b)); return d;
}
__device__ __forceinline__ uint bf2(float lo, float hi) {
    uint r; asm("cvt.rn.bf16x2.f32 %0,%1,%2;" : "=r"(r) : "f"(hi), "f"(lo)); return r;
}
// bf16x2 word -> packed f32x2 (ull): lo half -> low float, hi half -> high float
__device__ __forceinline__ ull bfp2(uint u) {
    return ((ull)(u & 0xffff0000u) << 32) | ((ull)(u << 16));
}
__device__ __forceinline__ uint tf32(float x) {
    uint r; asm("cvt.rna.tf32.f32 %0,%1;" : "=r"(r) : "f"(x)); return r;
}
__device__ __forceinline__ float tf32f(float x) { return __uint_as_float(tf32(x)); }
__device__ __forceinline__ void mma1688(float* c, uint a0, uint a1, uint a2, uint a3,
                                        uint b0, uint b1) {
    asm volatile("mma.sync.aligned.m16n8k8.row.col.f32.tf32.tf32.f32 "
        "{%0,%1,%2,%3},{%4,%5,%6,%7},{%8,%9},{%0,%1,%2,%3};"
        : "+f"(c[0]), "+f"(c[1]), "+f"(c[2]), "+f"(c[3])
        : "r"(a0), "r"(a1), "r"(a2), "r"(a3), "r"(b0), "r"(b1));
}
__device__ __forceinline__ void mmaf(float* c, float a0, float a1, float a2, float a3,
                                     float b0, float b1) {
    mma1688(c, __float_as_uint(a0), __float_as_uint(a1), __float_as_uint(a2),
            __float_as_uint(a3), __float_as_uint(b0), __float_as_uint(b1));
}
__device__ __forceinline__ void cpa16(uint dst, const void* src) {
    asm volatile("cp.async.ca.shared.global [%0], [%1], 16;" :: "r"(dst), "l"(src));
}
#define CP_COMMIT() asm volatile("cp.async.commit_group;" ::: "memory")
#define CP_WAIT(N)  asm volatile("cp.async.wait_group %0;" :: "n"(N) : "memory")

// ---------------- scratch (device globals; zero-initialized at module load) ----------------
__device__ float  g_h   [NN * HID];
__device__ float  g_h2  [NN * HID];
__device__ float  g_tmp [NN * HID];
__device__ float  g_q   [NN * HID];
__device__ float  g_k   [NN * HID];
__device__ float  g_v   [NN * HID];
__device__ ushort g_hwbf[NN * HID];
__device__ float  g_wct [NLAYERS * HID * HID];
__device__ int    g_deg[NN];        // zero at invocation start (cleanup re-zeros)
__device__ int    g_rp [NN + 1];
__device__ int    g_cur[NN];
__device__ int    g_col[EE];        // stores BYTE offsets (src_node * 256)
__device__ float  g_dis[NN];
__device__ int    g_done[1];

// ---------------- kernel 1: hist (1024 thr) + scan (last-block, 1024x32) + wt ----------------
// blocks 0..255: histogram (4 edges/thread, 4096/block); last block scans with 1024 threads.
// blocks 256..267: transpose Wc -> WT (32 warps each).
__global__ __launch_bounds__(1024) void k_histscan_wt(const int* __restrict__ dst,
                        int* __restrict__ deg, int* __restrict__ rp,
                        int* __restrict__ cur, float* __restrict__ dis,
                        int* __restrict__ done,
                        const float* __restrict__ Wc, float* __restrict__ WT) {
    if (blockIdx.x >= 256) {
        int w = (blockIdx.x - 256) * 32 + (threadIdx.x >> 5);   // 0..383
        int l = w >> 7, f = w & 127;
        int lane = threadIdx.x & 31;
        const float* Wl = Wc + l * 16384;
        float4 v;
        v.x = __ldg(&Wl[(lane * 4 + 0) * 128 + f]);
        v.y = __ldg(&Wl[(lane * 4 + 1) * 128 + f]);
        v.z = __ldg(&Wl[(lane * 4 + 2) * 128 + f]);
        v.w = __ldg(&Wl[(lane * 4 + 3) * 128 + f]);
        *(float4*)&WT[(size_t)l * 16384 + f * 128 + lane * 4] = v;
        return;
    }
    int e = (blockIdx.x * 1024 + threadIdx.x) * 4;
    int4 d = *(const int4*)&dst[e];
    atomicAdd(&deg[d.x], 1);
    atomicAdd(&deg[d.y], 1);
    atomicAdd(&deg[d.z], 1);
    atomicAdd(&deg[d.w], 1);
    __threadfence();
    __shared__ int amLast;
    if (threadIdx.x == 0)
        amLast = (atomicAdd(done, 1) == 255);
    __syncthreads();
    if (!amLast) return;

    // scan: 1024 threads x 32 nodes each
    __shared__ int part[1024];
    const int tid = threadIdx.x;
    const int base = tid * 32;
    int v[32];
    int s = 0;
    #pragma unroll
    for (int i = 0; i < 32; i++) { v[i] = deg[base + i]; s += v[i]; }
    part[tid] = s;
    __syncthreads();
    for (int off = 1; off < 1024; off <<= 1) {
        int t = (tid >= off) ? part[tid - off] : 0;
        __syncthreads();
        part[tid] += t;
        __syncthreads();
    }
    int run = part[tid] - s;
    #pragma unroll
    for (int i = 0; i < 32; i++) {
        rp[base + i]  = run;
        cur[base + i] = run;
        dis[base + i] = rsqrtf((float)v[i] + 1.0f);
        run += v[i];
    }
    if (tid == 1023) rp[NN] = run;
    if (tid == 0) *done = 0;
}

// ---------------- kernel 2: CSR fill (byte offsets) + input projection ----------------
__global__ __launch_bounds__(256) void k_fill_proj(const int* __restrict__ src,
                       const int* __restrict__ dst,
                       int* __restrict__ cur, int* __restrict__ col,
                       const float* __restrict__ x, const float* __restrict__ W,
                       const float* __restrict__ b, const float* __restrict__ g,
                       const float* __restrict__ be, float* __restrict__ out) {
    if (blockIdx.x < 1024) {
        int e = (blockIdx.x * 256 + threadIdx.x) * 4;
        int4 s = *(const int4*)&src[e];
        int4 d = *(const int4*)&dst[e];
        int p0 = atomicAdd(&cur[d.x], 1);
        int p1 = atomicAdd(&cur[d.y], 1);
        int p2 = atomicAdd(&cur[d.z], 1);
        int p3 = atomicAdd(&cur[d.w], 1);
        // store BYTE offset of the bf16 row: node * 128 * 2
        col[p0] = s.x << 8; col[p1] = s.y << 8;
        col[p2] = s.z << 8; col[p3] = s.w << 8;
        return;
    }
    const int lane = threadIdx.x & 31;
    const int n0 = ((blockIdx.x - 1024) * 8 + (threadIdx.x >> 5)) * 8;
    float4 w[15];
    #pragma unroll
    for (int k = 0; k < 15; k++) w[k] = *(const float4*)&W[k * 128 + lane * 4];
    const float4 bb = *(const float4*)&b[lane * 4];
    const float4 gv = *(const float4*)&g[lane * 4];
    const float4 bv = *(const float4*)&be[lane * 4];
    float4 xv = make_float4(0.f, 0.f, 0.f, 0.f);
    if (lane < 30) xv = *(const float4*)&x[n0 * 15 + lane * 4];

    #pragma unroll
    for (int i = 0; i < 8; i++) {
        float4 acc = bb;
        #pragma unroll
        for (int k = 0; k < 15; k++) {
            const int e = i * 15 + k;
            const int srcLane = e >> 2, comp = e & 3;
            float xe = (comp == 0) ? xv.x : (comp == 1) ? xv.y : (comp == 2) ? xv.z : xv.w;
            float xk = __shfl_sync(0xffffffffu, xe, srcLane);
            acc.x = fmaf(xk, w[k].x, acc.x); acc.y = fmaf(xk, w[k].y, acc.y);
            acc.z = fmaf(xk, w[k].z, acc.z); acc.w = fmaf(xk, w[k].w, acc.w);
        }
        float s  = acc.x + acc.y + acc.z + acc.w;
        float s2 = acc.x*acc.x + acc.y*acc.y + acc.z*acc.z + acc.w*acc.w;
        #pragma unroll
        for (int o = 16; o > 0; o >>= 1) {
            s  += __shfl_xor_sync(0xffffffffu, s,  o);
            s2 += __shfl_xor_sync(0xffffffffu, s2, o);
        }
        float m   = s * (1.0f / 128.0f);
        float var = s2 * (1.0f / 128.0f) - m * m;
        float r   = rsqrtf(var + 1e-5f);
        float4 y;
        y.x = fmaxf((acc.x - m) * r * gv.x + bv.x, 0.0f);
        y.y = fmaxf((acc.y - m) * r * gv.y + bv.y, 0.0f);
        y.z = fmaxf((acc.z - m) * r * gv.z + bv.z, 0.0f);
        y.w = fmaxf((acc.w - m) * r * gv.w + bv.w, 0.0f);
        *(float4*)(out + (size_t)(n0 + i) * 128 + lane * 4) = y;
    }
}

// ---------------- tf32 tensor-core GEMM (2-stage cp.async; R13 config) ----------------
#define STG_W 4096

__device__ __forceinline__ void stage_issue(uint smA, uint smB,
                                            const float* __restrict__ A,
                                            const float* __restrict__ B,
                                            int row0, int kt, int t) {
    #pragma unroll
    for (int i = 0; i < 4; i++) {
        int idx = i * 256 + t;
        int r = idx >> 3, c4 = (idx & 7) * 4;
        int cs = c4 ^ ((r & 7) << 2);
        cpa16(smA + (uint)(r * 32 + cs) * 4u, &A[(size_t)(row0 + r) * 128 + kt * 32 + c4]);
    }
    #pragma unroll
    for (int i = 0; i < 4; i++) {
        int idx = i * 256 + t;
        int r = idx >> 3, c4 = (idx & 7) * 4;
        int cs = c4 ^ ((r & 7) << 2);
        cpa16(smB + (uint)(r * 32 + cs) * 4u, &B[(size_t)r * 128 + kt * 32 + c4]);
    }
}

template <int BIAS, int BF16OUT>
__device__ __forceinline__ void tgemm_dev(uint* sm, const float* __restrict__ A,
                                          const float* __restrict__ B,
                                          const float* __restrict__ bias,
                                          const float* __restrict__ dis,
                                          void* __restrict__ Cv) {
    const int t = threadIdx.x;
    const int lane = t & 31, warp = t >> 5;
    const int row0 = blockIdx.x * 128;
    const int m0 = (warp >> 2) * 64;
    const int n0 = (warp & 3) * 32;
    const int gid = lane >> 2, tg = lane & 3;
    const uint smbase = (uint)__cvta_generic_to_shared(sm);

    stage_issue(smbase, smbase + STG_W * 4u, A, B, row0, 0, t);
    CP_COMMIT();
    stage_issue(smbase + 2u * STG_W * 4u, smbase + 3u * STG_W * 4u, A, B, row0, 1, t);
    CP_COMMIT();

    float acc[4][4][4];
    #pragma unroll
    for (int mi = 0; mi < 4; mi++)
        #pragma unroll
        for (int ni = 0; ni < 4; ni++)
            #pragma unroll
            for (int q = 0; q < 4; q++) acc[mi][ni][q] = 0.0f;

    #pragma unroll
    for (int kt = 0; kt < 4; kt++) {
        if (kt < 3) { CP_WAIT(1); } else { CP_WAIT(0); }
        __syncthreads();
        const uint* As = sm + (kt & 1) * 2 * STG_W;
        const uint* Bs = As + STG_W;
        #pragma unroll
        for (int ks = 0; ks < 4; ks++) {
            const int c0 = (ks * 8 + tg) ^ (gid << 2);
            const int c1 = c0 ^ 4;
            uint af[4][4];
            #pragma unroll
            for (int mi = 0; mi < 4; mi++) {
                const uint* a0 = &As[(m0 + mi * 16 + gid) * 32];
                const uint* a1 = &As[(m0 + mi * 16 + gid + 8) * 32];
                af[mi][0] = a0[c0]; af[mi][1] = a1[c0];
                af[mi][2] = a0[c1]; af[mi][3] = a1[c1];
            }
            uint bf[4][2];
            #pragma unroll
            for (int ni = 0; ni < 4; ni++) {
                const uint* b0 = &Bs[(n0 + ni * 8 + gid) * 32];
                bf[ni][0] = b0[c0]; bf[ni][1] = b0[c1];
            }
            #pragma unroll
            for (int mi = 0; mi < 4; mi++)
                #pragma unroll
                for (int ni = 0; ni < 4; ni++)
                    mma1688(acc[mi][ni], af[mi][0], af[mi][1], af[mi][2], af[mi][3],
                            bf[ni][0], bf[ni][1]);
        }
        __syncthreads();
        if (kt < 2) {
            int s = kt + 2;
            uint ab = smbase + (uint)(s & 1) * 2u * STG_W * 4u;
            stage_issue(ab, ab + STG_W * 4u, A, B, row0, s, t);
            CP_COMMIT();
        }
    }

    float2 bb[4];
    #pragma unroll
    for (int ni = 0; ni < 4; ni++) {
        if (BIAS) bb[ni] = *(const float2*)&bias[n0 + ni * 8 + tg * 2];
        else      bb[ni] = make_float2(0.f, 0.f);
    }
    #pragma unroll
    for (int mi = 0; mi < 4; mi++) {
        int r = row0 + m0 + mi * 16 + gid;
        float d0 = 1.0f, d1 = 1.0f;
        if (BF16OUT) { d0 = __ldg(&dis[r]); d1 = __ldg(&dis[r + 8]); }
        #pragma unroll
        for (int ni = 0; ni < 4; ni++) {
            int c = n0 + ni * 8 + tg * 2;
            float v0 = acc[mi][ni][0] + bb[ni].x;
            float v1 = acc[mi][ni][1] + bb[ni].y;
            float v2 = acc[mi][ni][2] + bb[ni].x;
            float v3 = acc[mi][ni][3] + bb[ni].y;
            if (BF16OUT) {
                ushort* Cb = (ushort*)Cv;
                *(uint*)(Cb + (size_t)r * 128 + c)       = bf2(v0 * d0, v1 * d0);
                *(uint*)(Cb + (size_t)(r + 8) * 128 + c) = bf2(v2 * d1, v3 * d1);
            } else {
                float* C = (float*)Cv;
                *(float2*)&C[(size_t)r * 128 + c]       = make_float2(v0, v1);
                *(float2*)&C[(size_t)(r + 8) * 128 + c] = make_float2(v2, v3);
            }
        }
    }
}

template <int BIAS, int BF16OUT>
__global__ __launch_bounds__(256, 2) void k_tgemm(const float* __restrict__ A,
                                                  const float* __restrict__ B,
                                                  const float* __restrict__ bias,
                                                  const float* __restrict__ dis,
                                                  void* __restrict__ C) {
    extern __shared__ uint smx[];
    tgemm_dev<BIAS, BF16OUT>(smx, A, B, bias, dis, C);
}

__global__ __launch_bounds__(256, 2) void k_tgemm_qkv(const float* __restrict__ A,
    const float* __restrict__ Wq, const float* __restrict__ bq, float* __restrict__ q,
    const float* __restrict__ Wk, const float* __restrict__ bk, float* __restrict__ k,
    const float* __restrict__ Wv, const float* __restrict__ bv, float* __restrict__ v) {
    extern __shared__ uint smx[];
    int s = blockIdx.y;
    const float* B  = (s == 0) ? Wq : (s == 1) ? Wk : Wv;
    const float* bi = (s == 0) ? bq : (s == 1) ? bk : bv;
    float*       C  = (s == 0) ? q  : (s == 1) ? k  : v;
    tgemm_dev<1, 0>(smx, A, B, bi, nullptr, C);
}

// ---------------- GCN aggregate (pre-scaled bf16 rows; byte-offset col) ----------------
__global__ __launch_bounds__(128) void k_gcn_agg(const ushort* __restrict__ hw,
                          const float* __restrict__ hin,
                          const int* __restrict__ rp, const int* __restrict__ col,
                          const float* __restrict__ dis,
                          const float* __restrict__ bc, const float* __restrict__ gn,
                          const float* __restrict__ bn, float* __restrict__ hout,
                          int residual) {
    const int lane = threadIdx.x & 31;
    const int n = blockIdx.x * 4 + (threadIdx.x >> 5);
    const float dn = dis[n];
    const char* hwb = (const char*)hw + lane * 8;   // lane-local base

    uint2 u = *(const uint2*)(hwb + ((size_t)n << 8));
    ull a0 = bfp2(u.x), a1 = bfp2(u.y);   // self row (already dis[n]-scaled)

    int e = rp[n], end = rp[n + 1];
    for (; e + 8 <= end; e += 8) {
        int   off[8];
        uint2 ui[8];
        #pragma unroll
        for (int q = 0; q < 8; q++) off[q] = __ldg(&col[e + q]);
        #pragma unroll
        for (int q = 0; q < 8; q++) ui[q] = *(const uint2*)(hwb + off[q]);
        #pragma unroll
        for (int q = 0; q < 8; q++) {
            a0 = add2(a0, bfp2(ui[q].x));
            a1 = add2(a1, bfp2(ui[q].y));
        }
    }
    for (; e < end; e++) {
        int off = __ldg(&col[e]);
        uint2 u0 = *(const uint2*)(hwb + off);
        a0 = add2(a0, bfp2(u0.x));
        a1 = add2(a1, bfp2(u0.y));
    }

    float x0, x1, x2, x3;
    up2(a0, x0, x1); up2(a1, x2, x3);
    float4 bcv = *(const float4*)&bc[lane * 4];
    x0 = fmaf(dn, x0, bcv.x); x1 = fmaf(dn, x1, bcv.y);
    x2 = fmaf(dn, x2, bcv.z); x3 = fmaf(dn, x3, bcv.w);

    float s  = x0 + x1 + x2 + x3;
    float s2 = x0 * x0 + x1 * x1 + x2 * x2 + x3 * x3;
    #pragma unroll
    for (int o = 16; o > 0; o >>= 1) {
        s  += __shfl_xor_sync(0xffffffffu, s,  o);
        s2 += __shfl_xor_sync(0xffffffffu, s2, o);
    }
    float m   = s  * (1.0f / 128.0f);
    float var = s2 * (1.0f / 128.0f) - m * m;
    float r   = rsqrtf(var + 1e-5f);

    float4 gv = *(const float4*)&gn[lane * 4];
    float4 bv = *(const float4*)&bn[lane * 4];
    float y0 = fmaxf((x0 - m) * r * gv.x + bv.x, 0.0f);
    float y1 = fmaxf((x1 - m) * r * gv.y + bv.y, 0.0f);
    float y2 = fmaxf((x2 - m) * r * gv.z + bv.z, 0.0f);
    float y3 = fmaxf((x3 - m) * r * gv.w + bv.w, 0.0f);
    if (residual) {
        float4 hr = *(const float4*)(hin + (size_t)n * 128 + lane * 4);
        y0 += hr.x; y1 += hr.y; y2 += hr.z; y3 += hr.w;
    }
    *(float4*)(hout + (size_t)n * 128 + lane * 4) = make_float4(y0, y1, y2, y3);
}

// ---------------- tensor-core flash attention (occ 3) ----------------
#define AT_KS 20
#define AT_VS 260
#define AT_PS 36
#define AT_KS_OFF 0
#define AT_VT_OFF (256 * AT_KS)
#define AT_PW_OFF (AT_VT_OFF + 16 * AT_VS)
#define AT_SMEM_W (AT_PW_OFF + 8 * 32 * AT_PS)
#define AT_SMEM_B (AT_SMEM_W * 4)

__global__ __launch_bounds__(256, 3) void k_attn_tc(const float* __restrict__ qg,
                                                    const float* __restrict__ kg,
                                                    const float* __restrict__ vg,
                                                    float* __restrict__ og) {
    extern __shared__ float smf[];
    float* Ks = smf + AT_KS_OFF;
    float* Vt = smf + AT_VT_OFF;
    const int t = threadIdx.x;
    const int lane = t & 31, warp = t >> 5;
    const int gid = lane >> 2, tg = lane & 3;
    float* Pw = smf + AT_PW_OFF + warp * (32 * AT_PS);
    const int g = blockIdx.x >> 3, h = blockIdx.x & 7;
    const size_t base = (size_t)(g * NPG) * 128 + h * 16;
    const float PRE = 0.25f * 1.4426950408889634f;

    {
        const float4* kp = (const float4*)(kg + base + (size_t)t * 128);
        float* kr = Ks + t * AT_KS;
        #pragma unroll
        for (int i = 0; i < 4; i++) {
            float4 v = kp[i];
            kr[i*4+0] = tf32f(v.x); kr[i*4+1] = tf32f(v.y);
            kr[i*4+2] = tf32f(v.z); kr[i*4+3] = tf32f(v.w);
        }
        const float4* vp = (const float4*)(vg + base + (size_t)t * 128);
        #pragma unroll
        for (int i = 0; i < 4; i++) {
            float4 v = vp[i];
            Vt[(i*4+0) * AT_VS + t] = tf32f(v.x);
            Vt[(i*4+1) * AT_VS + t] = tf32f(v.y);
            Vt[(i*4+2) * AT_VS + t] = tf32f(v.z);
            Vt[(i*4+3) * AT_VS + t] = tf32f(v.w);
        }
    }
    const int wm0 = warp * 32;
    float qf[2][8];
    #pragma unroll
    for (int mi = 0; mi < 2; mi++) {
        size_t r0 = (size_t)(g * NPG + wm0 + mi * 16 + gid) * 128 + h * 16;
        size_t r1 = r0 + 8 * 128;
        #pragma unroll
        for (int ks = 0; ks < 2; ks++) {
            qf[mi][ks*4+0] = tf32f(qg[r0 + ks*8 + tg]     * PRE);
            qf[mi][ks*4+1] = tf32f(qg[r1 + ks*8 + tg]     * PRE);
            qf[mi][ks*4+2] = tf32f(qg[r0 + ks*8 + tg + 4] * PRE);
            qf[mi][ks*4+3] = tf32f(qg[r1 + ks*8 + tg + 4] * PRE);
        }
    }
    __syncthreads();

    float oacc[2][2][4];
    float lacc[2][2];
    #pragma unroll
    for (int mi = 0; mi < 2; mi++) {
        lacc[mi][0] = 0.0f; lacc[mi][1] = 0.0f;
        #pragma unroll
        for (int ni = 0; ni < 2; ni++)
            #pragma unroll
            for (int q = 0; q < 4; q++) oacc[mi][ni][q] = 0.0f;
    }

    #pragma unroll 1
    for (int jt = 0; jt < 8; jt++) {
        const int j0 = jt * 32;
        float sacc[2][4][4];
        #pragma unroll
        for (int mi = 0; mi < 2; mi++)
            #pragma unroll
            for (int ni = 0; ni < 4; ni++)
                #pragma unroll
                for (int q = 0; q < 4; q++) sacc[mi][ni][q] = 0.0f;
        #pragma unroll
        for (int ks = 0; ks < 2; ks++) {
            float bf[4][2];
            #pragma unroll
            for (int ni = 0; ni < 4; ni++) {
                const float* kb = &Ks[(j0 + ni * 8 + gid) * AT_KS + ks * 8 + tg];
                bf[ni][0] = kb[0]; bf[ni][1] = kb[4];
            }
            #pragma unroll
            for (int mi = 0; mi < 2; mi++)
                #pragma unroll
                for (int ni = 0; ni < 4; ni++)
                    mmaf(sacc[mi][ni], qf[mi][ks*4+0], qf[mi][ks*4+1],
                         qf[mi][ks*4+2], qf[mi][ks*4+3], bf[ni][0], bf[ni][1]);
        }
        __syncwarp();
        #pragma unroll
        for (int mi = 0; mi < 2; mi++) {
            #pragma unroll
            for (int ni = 0; ni < 4; ni++) {
                float p0 = exp2f(sacc[mi][ni][0]);
                float p1 = exp2f(sacc[mi][ni][1]);
                float p2 = exp2f(sacc[mi][ni][2]);
                float p3 = exp2f(sacc[mi][ni][3]);
                lacc[mi][0] += p0 + p1;
                lacc[mi][1] += p2 + p3;
                int c = ni * 8 + tg * 2;
                *(float2*)&Pw[(mi * 16 + gid) * AT_PS + c]     = make_float2(p0, p1);
                *(float2*)&Pw[(mi * 16 + gid + 8) * AT_PS + c] = make_float2(p2, p3);
            }
        }
        __syncwarp();
        #pragma unroll
        for (int ks = 0; ks < 4; ks++) {
            float vb[2][2];
            #pragma unroll
            for (int ni = 0; ni < 2; ni++) {
                const float* vr = &Vt[(ni * 8 + gid) * AT_VS + j0 + ks * 8 + tg];
                vb[ni][0] = vr[0]; vb[ni][1] = vr[4];
            }
            float af[2][4];
            #pragma unroll
            for (int mi = 0; mi < 2; mi++) {
                const float* p0 = &Pw[(mi * 16 + gid) * AT_PS + ks * 8 + tg];
                const float* p1 = &Pw[(mi * 16 + gid + 8) * AT_PS + ks * 8 + tg];
                af[mi][0] = p0[0]; af[mi][1] = p1[0];
                af[mi][2] = p0[4]; af[mi][3] = p1[4];
            }
            #pragma unroll
            for (int mi = 0; mi < 2; mi++)
                #pragma unroll
                for (int ni = 0; ni < 2; ni++)
                    mmaf(oacc[mi][ni], af[mi][0], af[mi][1], af[mi][2], af[mi][3],
                         vb[ni][0], vb[ni][1]);
        }
        __syncwarp();
    }

    #pragma unroll
    for (int mi = 0; mi < 2; mi++) {
        #pragma unroll
        for (int u = 0; u < 2; u++) {
            float l = lacc[mi][u];
            l += __shfl_xor_sync(0xffffffffu, l, 1);
            l += __shfl_xor_sync(0xffffffffu, l, 2);
            lacc[mi][u] = 1.0f / l;
        }
    }
    #pragma unroll
    for (int mi = 0; mi < 2; mi++) {
        int r0 = g * NPG + wm0 + mi * 16 + gid;
        #pragma unroll
        for (int ni = 0; ni < 2; ni++) {
            int c = h * 16 + ni * 8 + tg * 2;
            *(float2*)&og[(size_t)r0 * 128 + c] =
                make_float2(oacc[mi][ni][0] * lacc[mi][0], oacc[mi][ni][1] * lacc[mi][0]);
            *(float2*)&og[(size_t)(r0 + 8) * 128 + c] =
                make_float2(oacc[mi][ni][2] * lacc[mi][1], oacc[mi][ni][3] * lacc[mi][1]);
        }
    }
}

// ---------------- fused: LN(out_proj + residual) -> pooling -> classifier (+deg cleanup) ----------------
__global__ __launch_bounds__(256) void k_lnpool_cls(const float* __restrict__ o2,
                          const float* __restrict__ hres,
                          const float* __restrict__ ga, const float* __restrict__ ba,
                          const float* __restrict__ W1, const float* __restrict__ b1,
                          const float* __restrict__ g1, const float* __restrict__ beta1,
                          const float* __restrict__ W2, const float* __restrict__ b2,
                          const float* __restrict__ W3, const float* __restrict__ b3,
                          float* __restrict__ out, int* __restrict__ deg) {
    if (blockIdx.x >= GG) {
        deg[(blockIdx.x - GG) * 256 + threadIdx.x] = 0;
        return;
    }
    __shared__ float ssum[8][128];
    __shared__ float smax[8][128];
    __shared__ float ps[384];
    __shared__ float z1[128];
    __shared__ float z2[64];
    __shared__ float red[8];
    const int g = blockIdx.x;
    const int w = threadIdx.x >> 5, lane = threadIdx.x & 31;
    {
        float4 gv = *(const float4*)&ga[lane * 4];
        float4 bv = *(const float4*)&ba[lane * 4];
        float4 psum = make_float4(0.f, 0.f, 0.f, 0.f);
        float4 pm = make_float4(-1e30f, -1e30f, -1e30f, -1e30f);
        #pragma unroll 2
        for (int i = 0; i < 32; i++) {
            size_t n = (size_t)g * NPG + w * 32 + i;
            float4 a = *(const float4*)(o2   + n * 128 + lane * 4);
            float4 b = *(const float4*)(hres + n * 128 + lane * 4);
            float x0 = a.x + b.x, x1 = a.y + b.y, x2 = a.z + b.z, x3 = a.w + b.w;
            float s  = x0 + x1 + x2 + x3;
            float s2 = x0*x0 + x1*x1 + x2*x2 + x3*x3;
            #pragma unroll
            for (int o = 16; o > 0; o >>= 1) {
                s  += __shfl_xor_sync(0xffffffffu, s,  o);
                s2 += __shfl_xor_sync(0xffffffffu, s2, o);
            }
            float m   = s  * (1.0f / 128.0f);
            float var = s2 * (1.0f / 128.0f) - m * m;
            float r   = rsqrtf(var + 1e-5f);
            float y0 = (x0 - m) * r * gv.x + bv.x;
            float y1 = (x1 - m) * r * gv.y + bv.y;
            float y2 = (x2 - m) * r * gv.z + bv.z;
            float y3 = (x3 - m) * r * gv.w + bv.w;
            psum.x += y0; psum.y += y1; psum.z += y2; psum.w += y3;
            pm.x = fmaxf(pm.x, y0); pm.y = fmaxf(pm.y, y1);
            pm.z = fmaxf(pm.z, y2); pm.w = fmaxf(pm.w, y3);
        }
        *(float4*)&ssum[w][lane * 4] = psum;
        *(float4*)&smax[w][lane * 4] = pm;
    }
    __syncthreads();
    {
        int f = threadIdx.x;
        if (f < 128) {
            float s = ssum[0][f], mx = smax[0][f];
            #pragma unroll
            for (int ww = 1; ww < 8; ww++) {
                s += ssum[ww][f];
                mx = fmaxf(mx, smax[ww][f]);
            }
            ps[f]       = s * (1.0f / 256.0f);
            ps[128 + f] = mx;
            ps[256 + f] = s;
        }
    }
    __syncthreads();
    const int f = threadIdx.x;
    float acc = 0.0f;
    if (f < 128) {
        acc = b1[f];
        for (int k = 0; k < 384; k++) acc = fmaf(ps[k], W1[k * 128 + f], acc);
    }
    {
        float s = (f < 128) ? acc : 0.0f;
        float s2 = s * s;
        #pragma unroll
        for (int o = 16; o > 0; o >>= 1) {
            s  += __shfl_xor_sync(0xffffffffu, s,  o);
            s2 += __shfl_xor_sync(0xffffffffu, s2, o);
        }
        if (w < 4 && lane == 0) { red[w] = s; red[4 + w] = s2; }
        __syncthreads();
        if (f < 128) {
            float ts  = red[0] + red[1] + red[2] + red[3];
            float ts2 = red[4] + red[5] + red[6] + red[7];
            float m   = ts  * (1.0f / 128.0f);
            float var = ts2 * (1.0f / 128.0f) - m * m;
            float r   = rsqrtf(var + 1e-5f);
            z1[f] = fmaxf((acc - m) * r * g1[f] + beta1[f], 0.0f);
        }
    }
    __syncthreads();
    if (f < 64) {
        float a = b2[f];
        #pragma unroll 8
        for (int k = 0; k < 128; k++) a = fmaf(z1[k], W2[k * 64 + f], a);
        z2[f] = fmaxf(a, 0.0f);
    }
    __syncthreads();
    if (f < 2) {
        float a = b3[f];
        #pragma unroll
        for (int k = 0; k < 64; k++) a = fmaf(z2[k], W3[k * 2 + f], a);
        out[g * 2 + f] = a;
    }
}

// ---------------- launch ----------------
extern "C" void kernel_launch(void* const* d_in, const int* in_sizes, int n_in,
                              void* d_out, int out_size) {
    const float* x     = (const float*)d_in[0];
    const int*   ei    = (const int*)  d_in[1];
    const float* W_in  = (const float*)d_in[3];
    const float* b_in  = (const float*)d_in[4];
    const float* g_in  = (const float*)d_in[5];
    const float* be_in = (const float*)d_in[6];
    const float* Wc    = (const float*)d_in[7];
    const float* bc    = (const float*)d_in[8];
    const float* gn    = (const float*)d_in[9];
    const float* bn    = (const float*)d_in[10];
    const float* Wq    = (const float*)d_in[11];
    const float* bq    = (const float*)d_in[12];
    const float* Wk    = (const float*)d_in[13];
    const float* bk    = (const float*)d_in[14];
    const float* Wv    = (const float*)d_in[15];
    const float* bv    = (const float*)d_in[16];
    const float* Wo    = (const float*)d_in[17];
    const float* bo    = (const float*)d_in[18];
    const float* ga    = (const float*)d_in[19];
    const float* ba    = (const float*)d_in[20];
    const float* W1    = (const float*)d_in[21];
    const float* b1    = (const float*)d_in[22];
    const float* g1    = (const float*)d_in[23];
    const float* beta1 = (const float*)d_in[24];
    const float* W2    = (const float*)d_in[25];
    const float* b2    = (const float*)d_in[26];
    const float* W3    = (const float*)d_in[27];
    const float* b3    = (const float*)d_in[28];
    float* out = (float*)d_out;

    const int* src = ei;
    const int* dst = ei + EE;

    float *p_h, *p_h2, *p_tmp, *p_q, *p_k, *p_v, *p_dis, *p_wct;
    ushort *p_hwbf;
    int *p_deg, *p_rp, *p_cur, *p_col, *p_done;
    cudaGetSymbolAddress((void**)&p_h,    g_h);
    cudaGetSymbolAddress((void**)&p_h2,   g_h2);
    cudaGetSymbolAddress((void**)&p_tmp,  g_tmp);
    cudaGetSymbolAddress((void**)&p_q,    g_q);
    cudaGetSymbolAddress((void**)&p_k,    g_k);
    cudaGetSymbolAddress((void**)&p_v,    g_v);
    cudaGetSymbolAddress((void**)&p_hwbf, g_hwbf);
    cudaGetSymbolAddress((void**)&p_wct,  g_wct);
    cudaGetSymbolAddress((void**)&p_deg,  g_deg);
    cudaGetSymbolAddress((void**)&p_rp,   g_rp);
    cudaGetSymbolAddress((void**)&p_cur,  g_cur);
    cudaGetSymbolAddress((void**)&p_col,  g_col);
    cudaGetSymbolAddress((void**)&p_dis,  g_dis);
    cudaGetSymbolAddress((void**)&p_done, g_done);

    const int HS = 4 * STG_W * sizeof(uint);   // 65536 B (2 stages x (A+B))
    cudaFuncSetAttribute(k_tgemm<0, 1>, cudaFuncAttributeMaxDynamicSharedMemorySize, HS);
    cudaFuncSetAttribute(k_tgemm<1, 0>, cudaFuncAttributeMaxDynamicSharedMemorySize, HS);
    cudaFuncSetAttribute(k_tgemm_qkv,   cudaFuncAttributeMaxDynamicSharedMemorySize, HS);
    cudaFuncSetAttribute(k_attn_tc,     cudaFuncAttributeMaxDynamicSharedMemorySize, AT_SMEM_B);

    // (1) hist+scan+wt  (2) fill+proj  (3) tgemm L1  (4) agg <- profiled
    k_histscan_wt<<<256 + 12, 1024>>>(dst, p_deg, p_rp, p_cur, p_dis, p_done, Wc, p_wct);
    k_fill_proj<<<1024 + 512, 256>>>(src, dst, p_cur, p_col,
                                     x, W_in, b_in, g_in, be_in, p_h);
    k_tgemm<0, 1><<<NN / 128, 256, HS>>>(p_h, p_wct, nullptr, p_dis, p_hwbf);
    k_gcn_agg<<<NN / 4, 128>>>(p_hwbf, p_h, p_rp, p_col, p_dis, bc, gn, bn, p_h2, 0);

    float* cur = p_h2;
    float* nxt = p_h;
    for (int i = 1; i < NLAYERS; i++) {
        k_tgemm<0, 1><<<NN / 128, 256, HS>>>(cur, p_wct + i * HID * HID, nullptr, p_dis, p_hwbf);
        k_gcn_agg<<<NN / 4, 128>>>(p_hwbf, cur, p_rp, p_col, p_dis,
                                   bc + i * HID, gn + i * HID, bn + i * HID, nxt, 1);
        float* t = cur; cur = nxt; nxt = t;
    }
    // cur == p_h2

    {
        dim3 grid(NN / 128, 3);
        k_tgemm_qkv<<<grid, 256, HS>>>(cur, Wq, bq, p_q, Wk, bk, p_k, Wv, bv, p_v);
    }
    k_attn_tc<<<GG * NH, 256, AT_SMEM_B>>>(p_q, p_k, p_v, p_tmp);
    k_tgemm<1, 0><<<NN / 128, 256, HS>>>(p_tmp, Wo, bo, nullptr, p_q);

    k_lnpool_cls<<<GG + 128, 256>>>(p_q, cur, ga, ba, W1, b1, g1, beta1,
                                    W2, b2, W3, b3, out, p_deg);
}